// round 1
// baseline (speedup 1.0000x reference)
#include <cuda_runtime.h>
#include <math.h>

#define C_IDS 8192
#define W_IDS 8192
#define DIM 128
#define TEMP_INV 10.0f   // 1 / temperature(0.1)
#define A0 0.5f
#define A1 0.5f

// ---------------- device scratch (static, no allocation) ----------------
__device__ float    g_csv_sum[C_IDS * DIM];            // 4 MB (becomes csv_emb * TEMP_INV)
__device__ float    g_wiki_sum[W_IDS * DIM];           // 4 MB (becomes wiki_emb)
__device__ float    g_csv_cnt[C_IDS];
__device__ float    g_wiki_cnt[W_IDS];
__device__ unsigned g_mask[(size_t)C_IDS * (W_IDS / 32)];   // 8 MB bitmask
__device__ float    g_logits[(size_t)C_IDS * W_IDS];        // 256 MB
__device__ float    g_acc[2];   // [0]=axis0 accumulator, [1]=axis1 accumulator

// ---------------- zero accumulators (graph-replayable determinism) ------
__global__ void zero_kernel() {
    size_t i = (size_t)blockIdx.x * blockDim.x + threadIdx.x;
    size_t stride = (size_t)gridDim.x * blockDim.x;
    for (size_t j = i; j < (size_t)C_IDS * DIM; j += stride) {
        g_csv_sum[j]  = 0.f;
        g_wiki_sum[j] = 0.f;
    }
    for (size_t j = i; j < C_IDS; j += stride) {
        g_csv_cnt[j]  = 0.f;
        g_wiki_cnt[j] = 0.f;
    }
    for (size_t j = i; j < (size_t)C_IDS * (W_IDS / 32); j += stride)
        g_mask[j] = 0u;
    if (i < 2) g_acc[i] = 0.f;
}

// ---------------- segment scatter-add + mask build ----------------------
// one warp per example row; 32 lanes x float4 covers D=128
__global__ void __launch_bounds__(256) scatter_kernel(
    const float* __restrict__ f1, const float* __restrict__ f2,
    const int* __restrict__ csv, const int* __restrict__ wiki, int n)
{
    int warp = threadIdx.x >> 5, lane = threadIdx.x & 31;
    int row = blockIdx.x * 8 + warp;
    if (row >= n) return;
    int c = csv[row];
    int w = wiki[row];

    float4 a = reinterpret_cast<const float4*>(f1 + (size_t)row * DIM)[lane];
    float4 b = reinterpret_cast<const float4*>(f2 + (size_t)row * DIM)[lane];

    float* cs = g_csv_sum + (size_t)c * DIM + lane * 4;
    atomicAdd(cs + 0, a.x); atomicAdd(cs + 1, a.y);
    atomicAdd(cs + 2, a.z); atomicAdd(cs + 3, a.w);

    float* ws = g_wiki_sum + (size_t)w * DIM + lane * 4;
    atomicAdd(ws + 0, b.x); atomicAdd(ws + 1, b.y);
    atomicAdd(ws + 2, b.z); atomicAdd(ws + 3, b.w);

    if (lane == 0) {
        atomicAdd(&g_csv_cnt[c], 1.f);
        atomicAdd(&g_wiki_cnt[w], 1.f);
        atomicOr(&g_mask[(size_t)c * (W_IDS / 32) + (w >> 5)], 1u << (w & 31));
    }
}

// ---------------- sums -> means (fold 1/T into csv side) ----------------
__global__ void finalize_emb_kernel() {
    int i = blockIdx.x * blockDim.x + threadIdx.x;
    if (i < C_IDS * DIM) {
        g_csv_sum[i]  = g_csv_sum[i]  / fmaxf(g_csv_cnt[i / DIM], 1.f) * TEMP_INV;
        g_wiki_sum[i] = g_wiki_sum[i] / fmaxf(g_wiki_cnt[i / DIM], 1.f);
    }
}

// ---------------- fp32 GEMM: logits = csv_emb @ wiki_emb^T --------------
// 128x128 tile per block, BK=32, 8x8 per thread, 256 threads.
#define BM 128
#define BN 128
#define BK 32
#define TM 8
#define TN 8
#define SPAD 4

__global__ void __launch_bounds__(256) gemm_kernel() {
    __shared__ float As[BK][BM + SPAD];
    __shared__ float Bs[BK][BN + SPAD];

    int t  = threadIdx.x;
    int tx = t & 15;     // 0..15  (N direction)
    int ty = t >> 4;     // 0..15  (M direction)

    const float* A = g_csv_sum  + (size_t)blockIdx.y * BM * DIM;
    const float* B = g_wiki_sum + (size_t)blockIdx.x * BN * DIM;

    float acc[TM][TN];
#pragma unroll
    for (int i = 0; i < TM; i++)
#pragma unroll
        for (int j = 0; j < TN; j++) acc[i][j] = 0.f;

    for (int kk = 0; kk < DIM; kk += BK) {
#pragma unroll
        for (int i = 0; i < 4; i++) {
            int id   = t + i * 256;       // 0..1023
            int rrow = id >> 3;           // 0..127
            int c4   = id & 7;            // 0..7
            float4 qa = *reinterpret_cast<const float4*>(A + (size_t)rrow * DIM + kk + c4 * 4);
            As[c4 * 4 + 0][rrow] = qa.x;
            As[c4 * 4 + 1][rrow] = qa.y;
            As[c4 * 4 + 2][rrow] = qa.z;
            As[c4 * 4 + 3][rrow] = qa.w;
            float4 qb = *reinterpret_cast<const float4*>(B + (size_t)rrow * DIM + kk + c4 * 4);
            Bs[c4 * 4 + 0][rrow] = qb.x;
            Bs[c4 * 4 + 1][rrow] = qb.y;
            Bs[c4 * 4 + 2][rrow] = qb.z;
            Bs[c4 * 4 + 3][rrow] = qb.w;
        }
        __syncthreads();
#pragma unroll
        for (int k = 0; k < BK; k++) {
            float a[TM], b[TN];
            float4 a0 = *reinterpret_cast<const float4*>(&As[k][ty * TM]);
            float4 a1 = *reinterpret_cast<const float4*>(&As[k][ty * TM + 4]);
            a[0]=a0.x; a[1]=a0.y; a[2]=a0.z; a[3]=a0.w;
            a[4]=a1.x; a[5]=a1.y; a[6]=a1.z; a[7]=a1.w;
            float4 b0 = *reinterpret_cast<const float4*>(&Bs[k][tx * TN]);
            float4 b1 = *reinterpret_cast<const float4*>(&Bs[k][tx * TN + 4]);
            b[0]=b0.x; b[1]=b0.y; b[2]=b0.z; b[3]=b0.w;
            b[4]=b1.x; b[5]=b1.y; b[6]=b1.z; b[7]=b1.w;
#pragma unroll
            for (int i = 0; i < TM; i++)
#pragma unroll
                for (int j = 0; j < TN; j++)
                    acc[i][j] = fmaf(a[i], b[j], acc[i][j]);
        }
        __syncthreads();
    }

    float* Cp = g_logits + ((size_t)blockIdx.y * BM + ty * TM) * W_IDS
                         + (size_t)blockIdx.x * BN + tx * TN;
#pragma unroll
    for (int i = 0; i < TM; i++) {
        float4 q0 = make_float4(acc[i][0], acc[i][1], acc[i][2], acc[i][3]);
        float4 q1 = make_float4(acc[i][4], acc[i][5], acc[i][6], acc[i][7]);
        *reinterpret_cast<float4*>(Cp + (size_t)i * W_IDS)     = q0;
        *reinterpret_cast<float4*>(Cp + (size_t)i * W_IDS + 4) = q1;
    }
}

// ---------------- row pass (axis1): LSE over w + masked sums ------------
__global__ void __launch_bounds__(256) row_reduce_kernel() {
    __shared__ float red[256];
    int r = blockIdx.x, t = threadIdx.x;
    const float* row = g_logits + (size_t)r * W_IDS + t * 32;

    float v[32];
#pragma unroll
    for (int i = 0; i < 8; i++) {
        float4 q = reinterpret_cast<const float4*>(row)[i];
        v[4*i+0] = q.x; v[4*i+1] = q.y; v[4*i+2] = q.z; v[4*i+3] = q.w;
    }
    float m = v[0];
#pragma unroll
    for (int i = 1; i < 32; i++) m = fmaxf(m, v[i]);

    red[t] = m; __syncthreads();
    for (int s = 128; s > 0; s >>= 1) {
        if (t < s) red[t] = fmaxf(red[t], red[t + s]);
        __syncthreads();
    }
    float M = red[0]; __syncthreads();

    float se = 0.f;
#pragma unroll
    for (int i = 0; i < 32; i++) se += __expf(v[i] - M);

    unsigned wd = g_mask[(size_t)r * (W_IDS / 32) + t];
    float S = 0.f, cnt = 0.f;
#pragma unroll
    for (int i = 0; i < 32; i++)
        if ((wd >> i) & 1u) { S += v[i]; cnt += 1.f; }

    red[t] = se; __syncthreads();
    for (int s = 128; s > 0; s >>= 1) { if (t < s) red[t] += red[t + s]; __syncthreads(); }
    float SE = red[0]; __syncthreads();

    red[t] = S; __syncthreads();
    for (int s = 128; s > 0; s >>= 1) { if (t < s) red[t] += red[t + s]; __syncthreads(); }
    float Ssum = red[0]; __syncthreads();

    red[t] = cnt; __syncthreads();
    for (int s = 128; s > 0; s >>= 1) { if (t < s) red[t] += red[t + s]; __syncthreads(); }
    float CN = red[0];

    if (t == 0) {
        float lse = M + logf(SE);
        atomicAdd(&g_acc[1], (Ssum - CN * lse) / fmaxf(CN, 1.f));
    }
}

// ---------------- col pass (axis0): LSE over c + masked sums ------------
// block b handles columns [32b, 32b+32); 8 warps stride the 8192 rows.
__global__ void __launch_bounds__(256) col_reduce_kernel() {
    __shared__ float sm[8][32];
    __shared__ float cmax[32];
    __shared__ float cse[32];
    __shared__ float cS[32];

    int t = threadIdx.x, warp = t >> 5, lane = t & 31;
    int b = blockIdx.x;
    size_t col = (size_t)b * 32 + lane;

    float m = -3.0e38f;
    for (int r = warp; r < C_IDS; r += 8)
        m = fmaxf(m, g_logits[(size_t)r * W_IDS + col]);
    sm[warp][lane] = m; __syncthreads();
    if (warp == 0) {
        float x = sm[0][lane];
#pragma unroll
        for (int i = 1; i < 8; i++) x = fmaxf(x, sm[i][lane]);
        cmax[lane] = x;
    }
    __syncthreads();
    float M = cmax[lane];

    float se = 0.f, S = 0.f, cnt = 0.f;
    for (int r = warp; r < C_IDS; r += 8) {
        float x = g_logits[(size_t)r * W_IDS + col];
        se += __expf(x - M);
        unsigned wd = g_mask[(size_t)r * (W_IDS / 32) + b];
        if ((wd >> lane) & 1u) { S += x; cnt += 1.f; }
    }

    __syncthreads();
    sm[warp][lane] = se; __syncthreads();
    if (warp == 0) {
        float x = 0.f;
#pragma unroll
        for (int i = 0; i < 8; i++) x += sm[i][lane];
        cse[lane] = x;
    }
    __syncthreads();
    sm[warp][lane] = S; __syncthreads();
    if (warp == 0) {
        float x = 0.f;
#pragma unroll
        for (int i = 0; i < 8; i++) x += sm[i][lane];
        cS[lane] = x;
    }
    __syncthreads();
    sm[warp][lane] = cnt; __syncthreads();
    if (warp == 0) {
        float cn = 0.f;
#pragma unroll
        for (int i = 0; i < 8; i++) cn += sm[i][lane];
        float lse = M + logf(cse[lane]);
        atomicAdd(&g_acc[0], (cS[lane] - cn * lse) / fmaxf(cn, 1.f));
    }
}

// ---------------- combine scalar ----------------------------------------
__global__ void final_kernel(float* out) {
    out[0] = -(A0 * g_acc[0] / (float)W_IDS + A1 * g_acc[1] / (float)C_IDS);
}

// ---------------- launch -------------------------------------------------
extern "C" void kernel_launch(void* const* d_in, const int* in_sizes, int n_in,
                              void* d_out, int out_size) {
    const float* f1   = (const float*)d_in[0];
    const float* f2   = (const float*)d_in[1];
    const int*   csv  = (const int*)d_in[2];
    const int*   wiki = (const int*)d_in[3];
    int n = in_sizes[2];   // number of examples

    zero_kernel<<<2048, 256>>>();
    scatter_kernel<<<(n + 7) / 8, 256>>>(f1, f2, csv, wiki, n);
    finalize_emb_kernel<<<(C_IDS * DIM + 255) / 256, 256>>>();

    dim3 g(W_IDS / BN, C_IDS / BM);
    gemm_kernel<<<g, 256>>>();

    row_reduce_kernel<<<C_IDS, 256>>>();
    col_reduce_kernel<<<W_IDS / 32, 256>>>();
    final_kernel<<<1, 1>>>((float*)d_out);
}

// round 2
// speedup vs baseline: 1.3223x; 1.3223x over previous
#include <cuda_runtime.h>
#include <math.h>

#define C_IDS 8192
#define W_IDS 8192
#define DIM 128
#define TEMP_INV 10.0f   // 1 / temperature(0.1)
#define A0 0.5f
#define A1 0.5f

#define NTILE 64         // 8192 / 128 tiles in each direction

// ---------------- device scratch (static, no allocation) ----------------
__device__ float    g_csv_sum[C_IDS * DIM];            // 4 MB (becomes csv_emb * TEMP_INV)
__device__ float    g_wiki_sum[W_IDS * DIM];           // 4 MB
__device__ float    g_csv_cnt[C_IDS];
__device__ float    g_wiki_cnt[W_IDS];
__device__ unsigned g_mask[(size_t)C_IDS * (W_IDS / 32)];   // 8 MB bitmask
// per-tile LSE partials
__device__ float    g_row_m[(size_t)C_IDS * NTILE];    // 2 MB
__device__ float    g_row_s[(size_t)C_IDS * NTILE];    // 2 MB
__device__ float    g_col_m[(size_t)W_IDS * NTILE];    // 2 MB
__device__ float    g_col_s[(size_t)W_IDS * NTILE];    // 2 MB
// masked logit sums
__device__ float    g_rowS[C_IDS];
__device__ float    g_colS[W_IDS];
__device__ float    g_colCnt[W_IDS];
__device__ float    g_acc[2];   // [0]=axis0 accumulator, [1]=axis1 accumulator

// ---------------- zero accumulators -------------------------------------
__global__ void zero_kernel() {
    size_t i = (size_t)blockIdx.x * blockDim.x + threadIdx.x;
    size_t stride = (size_t)gridDim.x * blockDim.x;
    for (size_t j = i; j < (size_t)C_IDS * DIM; j += stride) {
        g_csv_sum[j]  = 0.f;
        g_wiki_sum[j] = 0.f;
    }
    for (size_t j = i; j < C_IDS; j += stride) {
        g_csv_cnt[j]  = 0.f;
        g_wiki_cnt[j] = 0.f;
        g_rowS[j]     = 0.f;
        g_colS[j]     = 0.f;
    }
    for (size_t j = i; j < (size_t)C_IDS * (W_IDS / 32); j += stride)
        g_mask[j] = 0u;
    if (i < 2) g_acc[i] = 0.f;
}

// ---------------- segment scatter-add + mask build ----------------------
__global__ void __launch_bounds__(256) scatter_kernel(
    const float* __restrict__ f1, const float* __restrict__ f2,
    const int* __restrict__ csv, const int* __restrict__ wiki, int n)
{
    int warp = threadIdx.x >> 5, lane = threadIdx.x & 31;
    int row = blockIdx.x * 8 + warp;
    if (row >= n) return;
    int c = csv[row];
    int w = wiki[row];

    float4 a = reinterpret_cast<const float4*>(f1 + (size_t)row * DIM)[lane];
    float4 b = reinterpret_cast<const float4*>(f2 + (size_t)row * DIM)[lane];

    float* cs = g_csv_sum + (size_t)c * DIM + lane * 4;
    atomicAdd(cs + 0, a.x); atomicAdd(cs + 1, a.y);
    atomicAdd(cs + 2, a.z); atomicAdd(cs + 3, a.w);

    float* ws = g_wiki_sum + (size_t)w * DIM + lane * 4;
    atomicAdd(ws + 0, b.x); atomicAdd(ws + 1, b.y);
    atomicAdd(ws + 2, b.z); atomicAdd(ws + 3, b.w);

    if (lane == 0) {
        atomicAdd(&g_csv_cnt[c], 1.f);
        atomicAdd(&g_wiki_cnt[w], 1.f);
        atomicOr(&g_mask[(size_t)c * (W_IDS / 32) + (w >> 5)], 1u << (w & 31));
    }
}

// ---------------- sums -> means (fold 1/T into csv side) ----------------
__global__ void finalize_emb_kernel() {
    int i = blockIdx.x * blockDim.x + threadIdx.x;
    if (i < C_IDS * DIM) {
        g_csv_sum[i]  = g_csv_sum[i]  / fmaxf(g_csv_cnt[i / DIM], 1.f) * TEMP_INV;
        g_wiki_sum[i] = g_wiki_sum[i] / fmaxf(g_wiki_cnt[i / DIM], 1.f);
    }
}

// ---------------- fused GEMM + tile-local softmax partials --------------
// 128x128 tile per block, BK=32, 8x8 per thread, 256 threads.
#define BM 128
#define BN 128
#define BK 32
#define TM 8
#define TN 8
#define SPAD 4

__global__ void __launch_bounds__(256) gemm_kernel() {
    __shared__ float As[BK][BM + SPAD];
    __shared__ float Bs[BK][BN + SPAD];

    int t  = threadIdx.x;
    int tx = t & 15;     // 0..15  (N / col direction)
    int ty = t >> 4;     // 0..15  (M / row direction)
    int bx = blockIdx.x; // col tile
    int by = blockIdx.y; // row tile

    const float* A = g_csv_sum  + (size_t)by * BM * DIM;
    const float* B = g_wiki_sum + (size_t)bx * BN * DIM;

    float acc[TM][TN];
#pragma unroll
    for (int i = 0; i < TM; i++)
#pragma unroll
        for (int j = 0; j < TN; j++) acc[i][j] = 0.f;

    for (int kk = 0; kk < DIM; kk += BK) {
#pragma unroll
        for (int i = 0; i < 4; i++) {
            int id   = t + i * 256;
            int rrow = id >> 3;
            int c4   = id & 7;
            float4 qa = *reinterpret_cast<const float4*>(A + (size_t)rrow * DIM + kk + c4 * 4);
            As[c4 * 4 + 0][rrow] = qa.x;
            As[c4 * 4 + 1][rrow] = qa.y;
            As[c4 * 4 + 2][rrow] = qa.z;
            As[c4 * 4 + 3][rrow] = qa.w;
            float4 qb = *reinterpret_cast<const float4*>(B + (size_t)rrow * DIM + kk + c4 * 4);
            Bs[c4 * 4 + 0][rrow] = qb.x;
            Bs[c4 * 4 + 1][rrow] = qb.y;
            Bs[c4 * 4 + 2][rrow] = qb.z;
            Bs[c4 * 4 + 3][rrow] = qb.w;
        }
        __syncthreads();
#pragma unroll
        for (int k = 0; k < BK; k++) {
            float a[TM], b[TN];
            float4 a0 = *reinterpret_cast<const float4*>(&As[k][ty * TM]);
            float4 a1 = *reinterpret_cast<const float4*>(&As[k][ty * TM + 4]);
            a[0]=a0.x; a[1]=a0.y; a[2]=a0.z; a[3]=a0.w;
            a[4]=a1.x; a[5]=a1.y; a[6]=a1.z; a[7]=a1.w;
            float4 b0 = *reinterpret_cast<const float4*>(&Bs[k][tx * TN]);
            float4 b1 = *reinterpret_cast<const float4*>(&Bs[k][tx * TN + 4]);
            b[0]=b0.x; b[1]=b0.y; b[2]=b0.z; b[3]=b0.w;
            b[4]=b1.x; b[5]=b1.y; b[6]=b1.z; b[7]=b1.w;
#pragma unroll
            for (int i = 0; i < TM; i++)
#pragma unroll
                for (int j = 0; j < TN; j++)
                    acc[i][j] = fmaf(a[i], b[j], acc[i][j]);
        }
        __syncthreads();
    }

    // ---------- epilogue: per-row (m,s) partials (shuffle over 16 lanes) ----
#pragma unroll
    for (int i = 0; i < TM; i++) {
        float m = acc[i][0];
#pragma unroll
        for (int j = 1; j < TN; j++) m = fmaxf(m, acc[i][j]);
#pragma unroll
        for (int o = 8; o >= 1; o >>= 1)
            m = fmaxf(m, __shfl_xor_sync(0xFFFFFFFFu, m, o, 16));
        float s = 0.f;
#pragma unroll
        for (int j = 0; j < TN; j++) s += __expf(acc[i][j] - m);
#pragma unroll
        for (int o = 8; o >= 1; o >>= 1)
            s += __shfl_xor_sync(0xFFFFFFFFu, s, o, 16);
        if (tx == 0) {
            int row = by * BM + ty * TM + i;
            g_row_m[(size_t)row * NTILE + bx] = m;
            g_row_s[(size_t)row * NTILE + bx] = s;
        }
    }

    // ---------- masked logit scatter (sparse; <=131072 bits total) ----------
#pragma unroll
    for (int i = 0; i < TM; i++) {
        int row = by * BM + ty * TM + i;
        int colbase = bx * BN + tx * TN;
        unsigned word = g_mask[(size_t)row * (W_IDS / 32) + (colbase >> 5)];
        unsigned bits = (word >> ((tx * TN) & 31)) & 0xFFu;
        while (bits) {
            int j = __ffs(bits) - 1;
            bits &= bits - 1;
            atomicAdd(&g_rowS[row], acc[i][j]);
            atomicAdd(&g_colS[colbase + j], acc[i][j]);
        }
    }

    // ---------- per-col (m,s) partials (smem reduce across ty) --------------
    float* ep = &As[0][0];   // reuse As/Bs storage: need 2048 + 128 floats
#pragma unroll
    for (int j = 0; j < TN; j++) {
        float m = acc[0][j];
#pragma unroll
        for (int i = 1; i < TM; i++) m = fmaxf(m, acc[i][j]);
        ep[ty * 128 + tx * TN + j] = m;
    }
    __syncthreads();
    if (t < 128) {
        float m = ep[t];
#pragma unroll
        for (int r = 1; r < 16; r++) m = fmaxf(m, ep[r * 128 + t]);
        ep[2048 + t] = m;
    }
    __syncthreads();
#pragma unroll
    for (int j = 0; j < TN; j++) {
        float M = ep[2048 + tx * TN + j];
        float s = 0.f;
#pragma unroll
        for (int i = 0; i < TM; i++) s += __expf(acc[i][j] - M);
        ep[ty * 128 + tx * TN + j] = s;   // safe: maxes live at offset 2048
    }
    __syncthreads();
    if (t < 128) {
        float s = ep[t];
#pragma unroll
        for (int r = 1; r < 16; r++) s += ep[r * 128 + t];
        int col = bx * BN + t;
        g_col_m[(size_t)col * NTILE + by] = ep[2048 + t];
        g_col_s[(size_t)col * NTILE + by] = s;
    }
}

// ---------------- column mask popcounts ----------------------------------
// block b: columns [32b, 32b+32). warp w strides rows; lane = bit = column.
__global__ void __launch_bounds__(256) col_cnt_kernel() {
    __shared__ float sc[8][32];
    int t = threadIdx.x, warp = t >> 5, lane = t & 31;
    int b = blockIdx.x;
    float c = 0.f;
    for (int r = warp; r < C_IDS; r += 8) {
        unsigned w = g_mask[(size_t)r * (W_IDS / 32) + b];
        c += (float)((w >> lane) & 1u);
    }
    sc[warp][lane] = c;
    __syncthreads();
    if (warp == 0) {
        float x = sc[0][lane];
#pragma unroll
        for (int i = 1; i < 8; i++) x += sc[i][lane];
        g_colCnt[b * 32 + lane] = x;
    }
}

// ---------------- row finalize: merge 64 (m,s), popcount, loss term ------
__global__ void __launch_bounds__(256) row_final_kernel() {
    int t = threadIdx.x, warp = t >> 5, lane = t & 31;
    int row = blockIdx.x * 8 + warp;

    // merge two partials per lane
    size_t base = (size_t)row * NTILE;
    float m1 = g_row_m[base + 2 * lane],     s1 = g_row_s[base + 2 * lane];
    float m2 = g_row_m[base + 2 * lane + 1], s2 = g_row_s[base + 2 * lane + 1];
    float m = fmaxf(m1, m2);
    float s = s1 * __expf(m1 - m) + s2 * __expf(m2 - m);
#pragma unroll
    for (int o = 16; o >= 1; o >>= 1) {
        float mo = __shfl_xor_sync(0xFFFFFFFFu, m, o);
        float so = __shfl_xor_sync(0xFFFFFFFFu, s, o);
        float M = fmaxf(m, mo);
        s = s * __expf(m - M) + so * __expf(mo - M);
        m = M;
    }

    float cnt = 0.f;
    for (int k = lane; k < W_IDS / 32; k += 32)
        cnt += (float)__popc(g_mask[(size_t)row * (W_IDS / 32) + k]);
#pragma unroll
    for (int o = 16; o >= 1; o >>= 1)
        cnt += __shfl_xor_sync(0xFFFFFFFFu, cnt, o);

    if (lane == 0) {
        float lse = m + logf(s);
        float S = g_rowS[row];
        atomicAdd(&g_acc[1], (S - cnt * lse) / fmaxf(cnt, 1.f));
    }
}

// ---------------- col finalize --------------------------------------------
__global__ void __launch_bounds__(256) col_final_kernel() {
    int t = threadIdx.x, warp = t >> 5, lane = t & 31;
    int col = blockIdx.x * 8 + warp;

    size_t base = (size_t)col * NTILE;
    float m1 = g_col_m[base + 2 * lane],     s1 = g_col_s[base + 2 * lane];
    float m2 = g_col_m[base + 2 * lane + 1], s2 = g_col_s[base + 2 * lane + 1];
    float m = fmaxf(m1, m2);
    float s = s1 * __expf(m1 - m) + s2 * __expf(m2 - m);
#pragma unroll
    for (int o = 16; o >= 1; o >>= 1) {
        float mo = __shfl_xor_sync(0xFFFFFFFFu, m, o);
        float so = __shfl_xor_sync(0xFFFFFFFFu, s, o);
        float M = fmaxf(m, mo);
        s = s * __expf(m - M) + so * __expf(mo - M);
        m = M;
    }

    if (lane == 0) {
        float lse = m + logf(s);
        float S = g_colS[col];
        float cnt = g_colCnt[col];
        atomicAdd(&g_acc[0], (S - cnt * lse) / fmaxf(cnt, 1.f));
    }
}

// ---------------- combine scalar ------------------------------------------
__global__ void final_kernel(float* out) {
    out[0] = -(A0 * g_acc[0] / (float)W_IDS + A1 * g_acc[1] / (float)C_IDS);
}

// ---------------- launch ---------------------------------------------------
extern "C" void kernel_launch(void* const* d_in, const int* in_sizes, int n_in,
                              void* d_out, int out_size) {
    const float* f1   = (const float*)d_in[0];
    const float* f2   = (const float*)d_in[1];
    const int*   csv  = (const int*)d_in[2];
    const int*   wiki = (const int*)d_in[3];
    int n = in_sizes[2];

    zero_kernel<<<2048, 256>>>();
    scatter_kernel<<<(n + 7) / 8, 256>>>(f1, f2, csv, wiki, n);
    finalize_emb_kernel<<<(C_IDS * DIM + 255) / 256, 256>>>();

    dim3 g(W_IDS / BN, C_IDS / BM);
    gemm_kernel<<<g, 256>>>();

    col_cnt_kernel<<<W_IDS / 32, 256>>>();
    row_final_kernel<<<C_IDS / 8, 256>>>();
    col_final_kernel<<<W_IDS / 8, 256>>>();
    final_kernel<<<1, 1>>>((float*)d_out);
}

// round 5
// speedup vs baseline: 1.7884x; 1.3525x over previous
#include <cuda_runtime.h>
#include <math.h>
#include <stdint.h>

#define C_IDS 8192
#define W_IDS 8192
#define DIM 128
#define TEMP_INV 10.0f   // 1 / temperature(0.1)
#define A0 0.5f
#define A1 0.5f

// ---------------- device scratch ----------------------------------------
__device__ float    g_csv_sum[C_IDS * DIM];
__device__ float    g_wiki_sum[W_IDS * DIM];
__device__ float    g_csv_cnt[C_IDS];
__device__ float    g_wiki_cnt[W_IDS];
__device__ unsigned g_mask[(size_t)C_IDS * (W_IDS / 32)];   // 8 MB bitmask
__device__ float    g_row_m[(size_t)C_IDS * 32];   // (gx,nw) partials
__device__ float    g_row_s[(size_t)C_IDS * 32];
__device__ float    g_col_m[(size_t)W_IDS * 128];  // (by,mw) partials
__device__ float    g_col_s[(size_t)W_IDS * 128];
__device__ float    g_rowS[C_IDS];    // masked logit sums
__device__ float    g_colS[W_IDS];
__device__ float    g_colCnt[W_IDS];
__device__ float    g_acc[2];

// ---------------- zero kernel --------------------------------------------
__global__ void zero_kernel() {
    size_t i = (size_t)blockIdx.x * blockDim.x + threadIdx.x;
    size_t stride = (size_t)gridDim.x * blockDim.x;
    for (size_t j = i; j < (size_t)C_IDS * DIM; j += stride) {
        g_csv_sum[j]  = 0.f;
        g_wiki_sum[j] = 0.f;
    }
    for (size_t j = i; j < C_IDS; j += stride) {
        g_csv_cnt[j]  = 0.f;
        g_wiki_cnt[j] = 0.f;
        g_rowS[j]     = 0.f;
        g_colS[j]     = 0.f;
    }
    for (size_t j = i; j < (size_t)C_IDS * (W_IDS / 32); j += stride)
        g_mask[j] = 0u;
    if (i < 2) g_acc[i] = 0.f;
}

// ---------------- segment scatter-add + mask build ------------------------
__global__ void __launch_bounds__(256) scatter_kernel(
    const float* __restrict__ f1, const float* __restrict__ f2,
    const int* __restrict__ csv, const int* __restrict__ wiki, int n)
{
    int warp = threadIdx.x >> 5, lane = threadIdx.x & 31;
    int row = blockIdx.x * 8 + warp;
    if (row >= n) return;
    int c = csv[row];
    int w = wiki[row];

    float4 a = reinterpret_cast<const float4*>(f1 + (size_t)row * DIM)[lane];
    float4 b = reinterpret_cast<const float4*>(f2 + (size_t)row * DIM)[lane];

    float* cs = g_csv_sum + (size_t)c * DIM + lane * 4;
    atomicAdd(cs + 0, a.x); atomicAdd(cs + 1, a.y);
    atomicAdd(cs + 2, a.z); atomicAdd(cs + 3, a.w);

    float* ws = g_wiki_sum + (size_t)w * DIM + lane * 4;
    atomicAdd(ws + 0, b.x); atomicAdd(ws + 1, b.y);
    atomicAdd(ws + 2, b.z); atomicAdd(ws + 3, b.w);

    if (lane == 0) {
        atomicAdd(&g_csv_cnt[c], 1.f);
        atomicAdd(&g_wiki_cnt[w], 1.f);
        atomicOr(&g_mask[(size_t)c * (W_IDS / 32) + (w >> 5)], 1u << (w & 31));
    }
}

__global__ void finalize_emb_kernel() {
    int i = blockIdx.x * blockDim.x + threadIdx.x;
    if (i < C_IDS * DIM) {
        g_csv_sum[i]  = g_csv_sum[i]  / fmaxf(g_csv_cnt[i / DIM], 1.f) * TEMP_INV;
        g_wiki_sum[i] = g_wiki_sum[i] / fmaxf(g_wiki_cnt[i / DIM], 1.f);
    }
}

// ---------------- tf32 helpers --------------------------------------------
__device__ __forceinline__ uint32_t to_tf32(float x) {
    uint32_t u;
    asm("cvt.rna.tf32.f32 %0, %1;" : "=r"(u) : "f"(x));
    return u;
}

__device__ __forceinline__ void mma_tf32(float* d, const uint4& a, const uint2& b) {
    asm volatile(
        "mma.sync.aligned.m16n8k8.row.col.f32.tf32.tf32.f32 "
        "{%0,%1,%2,%3}, {%4,%5,%6,%7}, {%8,%9}, {%0,%1,%2,%3};"
        : "+f"(d[0]), "+f"(d[1]), "+f"(d[2]), "+f"(d[3])
        : "r"(a.x), "r"(a.y), "r"(a.z), "r"(a.w), "r"(b.x), "r"(b.y));
}

// ---------------- smem layout ----------------------------------------------
// fragment-major A: [mt 0..7][ks 0..15][lane 0..31][4 u32]  = 64KB
// fragment-major B: [nt 0..15][ks 0..15][lane 0..31][2 u32] = 64KB (x2 buffers)
#define SM_A   0
#define SM_B0  65536
#define SM_B1  131072
#define SMEM_BYTES 196608

__device__ __forceinline__ void load_A_frag(const float4* __restrict__ src,
                                            uint32_t* dst, int tid) {
    for (int i = tid; i < 4096; i += 256) {
        int row = i >> 5, c4 = i & 31;
        float4 q = src[i];
        int mt = row >> 4, gid = row & 7, rh = (row >> 3) & 1;
        float vals[4] = {q.x, q.y, q.z, q.w};
#pragma unroll
        for (int j = 0; j < 4; j++) {
            int col = c4 * 4 + j;
            int ks = col >> 3;
            int lane = gid * 4 + (col & 3);
            int reg = rh + (((col >> 2) & 1) << 1);
            dst[(((mt * 16 + ks) * 32 + lane) << 2) + reg] = to_tf32(vals[j]);
        }
    }
}

__device__ __forceinline__ void load_B_frag(const float4* __restrict__ src,
                                            uint32_t* dst, int tid) {
    for (int i = tid; i < 4096; i += 256) {
        int nrow = i >> 5, c4 = i & 31;
        float4 q = src[i];
        int nt = nrow >> 3, lb = (nrow & 7) * 4;
        float vals[4] = {q.x, q.y, q.z, q.w};
#pragma unroll
        for (int j = 0; j < 4; j++) {
            int k = c4 * 4 + j;
            int ks = k >> 3;
            int lane = lb + (k & 3);
            int reg = (k >> 2) & 1;
            dst[(((nt * 16 + ks) * 32 + lane) << 1) + reg] = to_tf32(vals[j]);
        }
    }
}

// ---------------- tensor GEMM + fused shifted-exp partials -----------------
// grid (8, 64): CTA = row-tile by (128 rows) x col tiles gx*8..gx*8+7.
// 8 warps: mw = wid>>2 (2 in M), nw = wid&3 (4 in N); warp tile 64x32.
// d-reg: row = i*16 + (lane>>2) + 8*(r>>1); col = j*8 + 2*(lane&3) + (r&1)
__global__ void __launch_bounds__(256, 1) gemm_kernel() {
    extern __shared__ char smem[];
    int t = threadIdx.x, wid = t >> 5, lane = t & 31;
    int mw = wid >> 2, nw = wid & 3;
    int gx = blockIdx.x, by = blockIdx.y;

    load_A_frag((const float4*)(g_csv_sum + (size_t)by * 128 * DIM),
                (uint32_t*)(smem + SM_A), t);
    load_B_frag((const float4*)(g_wiki_sum + (size_t)(gx * 8) * 128 * DIM),
                (uint32_t*)(smem + SM_B0), t);
    __syncthreads();

    float m_run = -3.0e38f;
    float rs_run[4][2];
#pragma unroll
    for (int i = 0; i < 4; i++) { rs_run[i][0] = 0.f; rs_run[i][1] = 0.f; }

    int buf = 0;
    for (int tt = 0; tt < 8; tt++) {
        int bx = gx * 8 + tt;
        const uint4* Af = (const uint4*)(smem + SM_A);
        const uint2* Bf = (const uint2*)(smem + (buf ? SM_B1 : SM_B0));

        float acc[4][4][4];
#pragma unroll
        for (int i = 0; i < 4; i++)
#pragma unroll
            for (int j = 0; j < 4; j++)
#pragma unroll
                for (int r = 0; r < 4; r++) acc[i][j][r] = 0.f;

#pragma unroll 4
        for (int ks = 0; ks < 16; ks++) {
            uint4 a[4];
            uint2 b[4];
#pragma unroll
            for (int i = 0; i < 4; i++)
                a[i] = Af[((mw * 4 + i) * 16 + ks) * 32 + lane];
#pragma unroll
            for (int j = 0; j < 4; j++)
                b[j] = Bf[((nw * 4 + j) * 16 + ks) * 32 + lane];
#pragma unroll
            for (int i = 0; i < 4; i++)
#pragma unroll
                for (int j = 0; j < 4; j++)
                    mma_tf32(acc[i][j], a[i], b[j]);
        }

        if (tt < 7)
            load_B_frag((const float4*)(g_wiki_sum + (size_t)(bx + 1) * 128 * DIM),
                        (uint32_t*)(smem + (buf ? SM_B0 : SM_B1)), t);

        // ---- epilogue: warp-tile max (warp-uniform shift) -------------------
        float wm = acc[0][0][0];
#pragma unroll
        for (int i = 0; i < 4; i++)
#pragma unroll
            for (int j = 0; j < 4; j++)
#pragma unroll
                for (int r = 0; r < 4; r++) wm = fmaxf(wm, acc[i][j][r]);
#pragma unroll
        for (int o = 16; o >= 1; o >>= 1)
            wm = fmaxf(wm, __shfl_xor_sync(0xFFFFFFFFu, wm, o));

        // one exp per element; row & col sums from same e
        float rs[4][2], cs[4][2];
#pragma unroll
        for (int i = 0; i < 4; i++) { rs[i][0] = rs[i][1] = cs[i][0] = cs[i][1] = 0.f; }
#pragma unroll
        for (int i = 0; i < 4; i++)
#pragma unroll
            for (int j = 0; j < 4; j++)
#pragma unroll
                for (int r = 0; r < 4; r++) {
                    float e = __expf(acc[i][j][r] - wm);
                    rs[i][r >> 1] += e;
                    cs[j][r & 1]  += e;
                }

        // online row merge across tiles (warp-uniform rescale)
        {
            float M2 = fmaxf(m_run, wm);
            float scO = __expf(m_run - M2);
            float scN = __expf(wm - M2);
#pragma unroll
            for (int i = 0; i < 4; i++) {
                rs_run[i][0] = rs_run[i][0] * scO + rs[i][0] * scN;
                rs_run[i][1] = rs_run[i][1] * scO + rs[i][1] * scN;
            }
            m_run = M2;
        }

        // col partials: same wm across warp -> plain sum over row-lanes
#pragma unroll
        for (int j = 0; j < 4; j++)
#pragma unroll
            for (int p = 0; p < 2; p++) {
                float v = cs[j][p];
                v += __shfl_xor_sync(0xFFFFFFFFu, v, 4);
                v += __shfl_xor_sync(0xFFFFFFFFu, v, 8);
                v += __shfl_xor_sync(0xFFFFFFFFu, v, 16);
                if (lane < 4) {
                    int col_g = bx * 128 + nw * 32 + j * 8 + 2 * lane + p;
                    g_col_m[(size_t)col_g * 128 + by * 2 + mw] = wm;
                    g_col_s[(size_t)col_g * 128 + by * 2 + mw] = v;
                }
            }

        // masked raw-logit scatter (sparse)
        {
            int wordIdx = bx * 4 + nw;
#pragma unroll
            for (int i = 0; i < 4; i++)
#pragma unroll
                for (int h = 0; h < 2; h++) {
                    int row_g = by * 128 + mw * 64 + i * 16 + (lane >> 2) + 8 * h;
                    unsigned w = g_mask[(size_t)row_g * (W_IDS / 32) + wordIdx];
                    if (w) {
                        float sR = 0.f;
                        int any = 0;
#pragma unroll
                        for (int j = 0; j < 4; j++)
#pragma unroll
                            for (int p = 0; p < 2; p++) {
                                int bit = j * 8 + 2 * (lane & 3) + p;
                                if ((w >> bit) & 1u) {
                                    float x = acc[i][j][2 * h + p];
                                    sR += x;
                                    any = 1;
                                    atomicAdd(&g_colS[bx * 128 + nw * 32 + bit], x);
                                }
                            }
                        if (any) atomicAdd(&g_rowS[row_g], sR);
                    }
                }
        }

        __syncthreads();
        buf ^= 1;
    }

    // write row partials: reduce over the 4 lanes sharing a row
#pragma unroll
    for (int i = 0; i < 4; i++)
#pragma unroll
        for (int h = 0; h < 2; h++) {
            float v = rs_run[i][h];
            v += __shfl_xor_sync(0xFFFFFFFFu, v, 1);
            v += __shfl_xor_sync(0xFFFFFFFFu, v, 2);
            if ((lane & 3) == 0) {
                int row_g = by * 128 + mw * 64 + i * 16 + (lane >> 2) + 8 * h;
                g_row_m[(size_t)row_g * 32 + gx * 4 + nw] = m_run;
                g_row_s[(size_t)row_g * 32 + gx * 4 + nw] = v;
            }
        }
}

// ---------------- column mask popcounts ------------------------------------
__global__ void __launch_bounds__(256) col_cnt_kernel() {
    __shared__ float sc[8][32];
    int t = threadIdx.x, warp = t >> 5, lane = t & 31;
    int b = blockIdx.x;
    float c = 0.f;
    for (int r = warp; r < C_IDS; r += 8) {
        unsigned w = g_mask[(size_t)r * (W_IDS / 32) + b];
        c += (float)((w >> lane) & 1u);
    }
    sc[warp][lane] = c;
    __syncthreads();
    if (warp == 0) {
        float x = sc[0][lane];
#pragma unroll
        for (int i = 1; i < 8; i++) x += sc[i][lane];
        g_colCnt[b * 32 + lane] = x;
    }
}

// ---------------- row finalize: merge 32 (m,s) + popcount -------------------
__global__ void __launch_bounds__(256) row_final_kernel() {
    __shared__ float part[8];
    int t = threadIdx.x, warp = t >> 5, lane = t & 31;
    int row = blockIdx.x * 8 + warp;

    float m = g_row_m[(size_t)row * 32 + lane];
    float s = g_row_s[(size_t)row * 32 + lane];
#pragma unroll
    for (int o = 16; o >= 1; o >>= 1) {
        float mo = __shfl_xor_sync(0xFFFFFFFFu, m, o);
        float so = __shfl_xor_sync(0xFFFFFFFFu, s, o);
        float M = fmaxf(m, mo);
        s = s * __expf(m - M) + so * __expf(mo - M);
        m = M;
    }

    float cnt = 0.f;
    for (int k = lane; k < W_IDS / 32; k += 32)
        cnt += (float)__popc(g_mask[(size_t)row * (W_IDS / 32) + k]);
#pragma unroll
    for (int o = 16; o >= 1; o >>= 1)
        cnt += __shfl_xor_sync(0xFFFFFFFFu, cnt, o);

    if (lane == 0) {
        float lse = m + logf(s);
        part[warp] = (g_rowS[row] - cnt * lse) / fmaxf(cnt, 1.f);
    }
    __syncthreads();
    if (t == 0) {
        float x = 0.f;
#pragma unroll
        for (int i = 0; i < 8; i++) x += part[i];
        atomicAdd(&g_acc[1], x);
    }
}

// ---------------- col finalize: merge 128 (m,s) -----------------------------
__global__ void __launch_bounds__(256) col_final_kernel() {
    __shared__ float part[8];
    int t = threadIdx.x, warp = t >> 5, lane = t & 31;
    int col = blockIdx.x * 8 + warp;
    size_t base = (size_t)col * 128;

    float m = -3.0e38f, s = 0.f;
#pragma unroll
    for (int k = 0; k < 4; k++) {
        float m1 = g_col_m[base + k * 32 + lane];
        float s1 = g_col_s[base + k * 32 + lane];
        float M = fmaxf(m, m1);
        s = s * __expf(m - M) + s1 * __expf(m1 - M);
        m = M;
    }
#pragma unroll
    for (int o = 16; o >= 1; o >>= 1) {
        float mo = __shfl_xor_sync(0xFFFFFFFFu, m, o);
        float so = __shfl_xor_sync(0xFFFFFFFFu, s, o);
        float M = fmaxf(m, mo);
        s = s * __expf(m - M) + so * __expf(mo - M);
        m = M;
    }

    if (lane == 0) {
        float cnt = g_colCnt[col];
        float lse = m + logf(s);
        part[warp] = (g_colS[col] - cnt * lse) / fmaxf(cnt, 1.f);
    }
    __syncthreads();
    if (t == 0) {
        float x = 0.f;
#pragma unroll
        for (int i = 0; i < 8; i++) x += part[i];
        atomicAdd(&g_acc[0], x);
    }
}

__global__ void final_kernel(float* out) {
    out[0] = -(A0 * g_acc[0] / (float)W_IDS + A1 * g_acc[1] / (float)C_IDS);
}

// ---------------- launch -------------------------------------------------------
extern "C" void kernel_launch(void* const* d_in, const int* in_sizes, int n_in,
                              void* d_out, int out_size) {
    const float* f1   = (const float*)d_in[0];
    const float* f2   = (const float*)d_in[1];
    const int*   csv  = (const int*)d_in[2];
    const int*   wiki = (const int*)d_in[3];
    int n = in_sizes[2];

    static int attr_set = 0;
    if (!attr_set) {
        cudaFuncSetAttribute(gemm_kernel, cudaFuncAttributeMaxDynamicSharedMemorySize,
                             SMEM_BYTES);
        attr_set = 1;
    }

    zero_kernel<<<2048, 256>>>();
    scatter_kernel<<<(n + 7) / 8, 256>>>(f1, f2, csv, wiki, n);
    finalize_emb_kernel<<<(C_IDS * DIM + 255) / 256, 256>>>();

    gemm_kernel<<<dim3(8, 64), 256, SMEM_BYTES>>>();

    col_cnt_kernel<<<W_IDS / 32, 256>>>();
    row_final_kernel<<<C_IDS / 8, 256>>>();
    col_final_kernel<<<W_IDS / 8, 256>>>();
    final_kernel<<<1, 1>>>((float*)d_out);
}

// round 6
// speedup vs baseline: 1.9420x; 1.0859x over previous
#include <cuda_runtime.h>
#include <math.h>
#include <stdint.h>

#define C_IDS 8192
#define W_IDS 8192
#define DIM 128
#define TEMP_INV 10.0f   // 1 / temperature(0.1)
#define A0 0.5f
#define A1 0.5f

// ---------------- device scratch ----------------------------------------
__device__ float    g_csv_sum[C_IDS * DIM];
__device__ float    g_wiki_sum[W_IDS * DIM];
__device__ float    g_csv_cnt[C_IDS];
__device__ float    g_wiki_cnt[W_IDS];
__device__ unsigned g_mask[(size_t)C_IDS * (W_IDS / 32)];   // 8 MB bitmask
__device__ float    g_row_m[(size_t)C_IDS * 32];    // (gx,nw) partials
__device__ float    g_row_s[(size_t)C_IDS * 32];
__device__ float    g_col_m[(size_t)W_IDS * 256];   // (by,mw) partials
__device__ float    g_col_s[(size_t)W_IDS * 256];
__device__ float    g_rowS[C_IDS];    // masked logit sums
__device__ float    g_colS[W_IDS];
__device__ float    g_colCnt[W_IDS];
__device__ float    g_acc[2];

// ---------------- zero kernel --------------------------------------------
__global__ void zero_kernel() {
    size_t i = (size_t)blockIdx.x * blockDim.x + threadIdx.x;
    size_t stride = (size_t)gridDim.x * blockDim.x;
    for (size_t j = i; j < (size_t)C_IDS * DIM; j += stride) {
        g_csv_sum[j]  = 0.f;
        g_wiki_sum[j] = 0.f;
    }
    for (size_t j = i; j < C_IDS; j += stride) {
        g_csv_cnt[j]  = 0.f;
        g_wiki_cnt[j] = 0.f;
        g_rowS[j]     = 0.f;
        g_colS[j]     = 0.f;
    }
    for (size_t j = i; j < (size_t)C_IDS * (W_IDS / 32); j += stride)
        g_mask[j] = 0u;
    if (i < 2) g_acc[i] = 0.f;
}

// ---------------- segment scatter-add + mask build ------------------------
__global__ void __launch_bounds__(256) scatter_kernel(
    const float* __restrict__ f1, const float* __restrict__ f2,
    const int* __restrict__ csv, const int* __restrict__ wiki, int n)
{
    int warp = threadIdx.x >> 5, lane = threadIdx.x & 31;
    int row = blockIdx.x * 8 + warp;
    if (row >= n) return;
    int c = csv[row];
    int w = wiki[row];

    float4 a = reinterpret_cast<const float4*>(f1 + (size_t)row * DIM)[lane];
    float4 b = reinterpret_cast<const float4*>(f2 + (size_t)row * DIM)[lane];

    float* cs = g_csv_sum + (size_t)c * DIM + lane * 4;
    atomicAdd(cs + 0, a.x); atomicAdd(cs + 1, a.y);
    atomicAdd(cs + 2, a.z); atomicAdd(cs + 3, a.w);

    float* ws = g_wiki_sum + (size_t)w * DIM + lane * 4;
    atomicAdd(ws + 0, b.x); atomicAdd(ws + 1, b.y);
    atomicAdd(ws + 2, b.z); atomicAdd(ws + 3, b.w);

    if (lane == 0) {
        atomicAdd(&g_csv_cnt[c], 1.f);
        atomicAdd(&g_wiki_cnt[w], 1.f);
        atomicOr(&g_mask[(size_t)c * (W_IDS / 32) + (w >> 5)], 1u << (w & 31));
    }
}

__global__ void finalize_emb_kernel() {
    int i = blockIdx.x * blockDim.x + threadIdx.x;
    if (i < C_IDS * DIM) {
        g_csv_sum[i]  = g_csv_sum[i]  / fmaxf(g_csv_cnt[i / DIM], 1.f) * TEMP_INV;
        g_wiki_sum[i] = g_wiki_sum[i] / fmaxf(g_wiki_cnt[i / DIM], 1.f);
    }
}

// ---------------- tf32 helpers --------------------------------------------
__device__ __forceinline__ uint32_t to_tf32(float x) {
    uint32_t u;
    asm("cvt.rna.tf32.f32 %0, %1;" : "=r"(u) : "f"(x));
    return u;
}

__device__ __forceinline__ void mma_tf32(float* d, const uint4& a, const uint2& b) {
    asm volatile(
        "mma.sync.aligned.m16n8k8.row.col.f32.tf32.tf32.f32 "
        "{%0,%1,%2,%3}, {%4,%5,%6,%7}, {%8,%9}, {%0,%1,%2,%3};"
        : "+f"(d[0]), "+f"(d[1]), "+f"(d[2]), "+f"(d[3])
        : "r"(a.x), "r"(a.y), "r"(a.z), "r"(a.w), "r"(b.x), "r"(b.y));
}

// ---------------- smem layout ----------------------------------------------
// fragment-major A: [mt 0..7][ks 0..15][lane 0..31][4 u32]  = 64KB
// fragment-major B: [nt 0..15][ks 0..15][lane 0..31][2 u32] = 64KB (x2 buffers)
#define SM_A   0
#define SM_B0  65536
#define SM_B1  131072
#define SMEM_BYTES 196608
#define NTHREADS 512

__device__ __forceinline__ void load_A_frag(const float4* __restrict__ src,
                                            uint32_t* dst, int tid) {
    for (int i = tid; i < 4096; i += NTHREADS) {
        int row = i >> 5, c4 = i & 31;
        float4 q = src[i];
        int mt = row >> 4, gid = row & 7, rh = (row >> 3) & 1;
        float vals[4] = {q.x, q.y, q.z, q.w};
#pragma unroll
        for (int j = 0; j < 4; j++) {
            int col = c4 * 4 + j;
            int ks = col >> 3;
            int lane = gid * 4 + (col & 3);
            int reg = rh + (((col >> 2) & 1) << 1);
            dst[(((mt * 16 + ks) * 32 + lane) << 2) + reg] = to_tf32(vals[j]);
        }
    }
}

__device__ __forceinline__ void load_B_frag(const float4* __restrict__ src,
                                            uint32_t* dst, int tid) {
    for (int i = tid; i < 4096; i += NTHREADS) {
        int nrow = i >> 5, c4 = i & 31;
        float4 q = src[i];
        int nt = nrow >> 3, lb = (nrow & 7) * 4;
        float vals[4] = {q.x, q.y, q.z, q.w};
#pragma unroll
        for (int j = 0; j < 4; j++) {
            int k = c4 * 4 + j;
            int ks = k >> 3;
            int lane = lb + (k & 3);
            int reg = (k >> 2) & 1;
            dst[(((nt * 16 + ks) * 32 + lane) << 1) + reg] = to_tf32(vals[j]);
        }
    }
}

// ---------------- tensor GEMM + fused shifted-exp partials -----------------
// grid (8, 64): CTA = row-tile by (128 rows) x col tiles gx*8..gx*8+7.
// 16 warps: mw = wid>>2 (4 in M), nw = wid&3 (4 in N); warp tile 32x32.
// d-reg: row = mw*32 + i*16 + (lane>>2) + 8*(r>>1)
//        col = nw*32 + j*8 + 2*(lane&3) + (r&1)
__global__ void __launch_bounds__(NTHREADS, 1) gemm_kernel() {
    extern __shared__ char smem[];
    int t = threadIdx.x, wid = t >> 5, lane = t & 31;
    int mw = wid >> 2, nw = wid & 3;
    int gx = blockIdx.x, by = blockIdx.y;

    load_A_frag((const float4*)(g_csv_sum + (size_t)by * 128 * DIM),
                (uint32_t*)(smem + SM_A), t);
    load_B_frag((const float4*)(g_wiki_sum + (size_t)(gx * 8) * 128 * DIM),
                (uint32_t*)(smem + SM_B0), t);
    __syncthreads();

    float m_run = -3.0e38f;
    float rs_run[2][2];
    rs_run[0][0] = rs_run[0][1] = rs_run[1][0] = rs_run[1][1] = 0.f;

    int buf = 0;
    for (int tt = 0; tt < 8; tt++) {
        int bx = gx * 8 + tt;
        const uint4* Af = (const uint4*)(smem + SM_A);
        const uint2* Bf = (const uint2*)(smem + (buf ? SM_B1 : SM_B0));

        float acc[2][4][4];
#pragma unroll
        for (int i = 0; i < 2; i++)
#pragma unroll
            for (int j = 0; j < 4; j++)
#pragma unroll
                for (int r = 0; r < 4; r++) acc[i][j][r] = 0.f;

#pragma unroll 4
        for (int ks = 0; ks < 16; ks++) {
            uint4 a[2];
            uint2 b[4];
#pragma unroll
            for (int i = 0; i < 2; i++)
                a[i] = Af[((mw * 2 + i) * 16 + ks) * 32 + lane];
#pragma unroll
            for (int j = 0; j < 4; j++)
                b[j] = Bf[((nw * 4 + j) * 16 + ks) * 32 + lane];
#pragma unroll
            for (int i = 0; i < 2; i++)
#pragma unroll
                for (int j = 0; j < 4; j++)
                    mma_tf32(acc[i][j], a[i], b[j]);
        }

        if (tt < 7)
            load_B_frag((const float4*)(g_wiki_sum + (size_t)(bx + 1) * 128 * DIM),
                        (uint32_t*)(smem + (buf ? SM_B0 : SM_B1)), t);

        // prefetch mask words (hide L2 latency behind the max-reduce)
        unsigned mword[2][2];
        {
            int wordIdx = bx * 4 + nw;
#pragma unroll
            for (int i = 0; i < 2; i++)
#pragma unroll
                for (int h = 0; h < 2; h++) {
                    int row_g = by * 128 + mw * 32 + i * 16 + (lane >> 2) + 8 * h;
                    mword[i][h] = g_mask[(size_t)row_g * (W_IDS / 32) + wordIdx];
                }
        }

        // ---- warp-tile max (warp-uniform shift) ---------------------------
        float wm = acc[0][0][0];
#pragma unroll
        for (int i = 0; i < 2; i++)
#pragma unroll
            for (int j = 0; j < 4; j++)
#pragma unroll
                for (int r = 0; r < 4; r++) wm = fmaxf(wm, acc[i][j][r]);
#pragma unroll
        for (int o = 16; o >= 1; o >>= 1)
            wm = fmaxf(wm, __shfl_xor_sync(0xFFFFFFFFu, wm, o));

        // one exp per element; row & col sums from same e
        float rs[2][2], cs[4][2];
#pragma unroll
        for (int i = 0; i < 2; i++) { rs[i][0] = rs[i][1] = 0.f; }
#pragma unroll
        for (int j = 0; j < 4; j++) { cs[j][0] = cs[j][1] = 0.f; }
#pragma unroll
        for (int i = 0; i < 2; i++)
#pragma unroll
            for (int j = 0; j < 4; j++)
#pragma unroll
                for (int r = 0; r < 4; r++) {
                    float e = __expf(acc[i][j][r] - wm);
                    rs[i][r >> 1] += e;
                    cs[j][r & 1]  += e;
                }

        // online row merge across tiles (warp-uniform rescale)
        {
            float M2 = fmaxf(m_run, wm);
            float scO = __expf(m_run - M2);
            float scN = __expf(wm - M2);
#pragma unroll
            for (int i = 0; i < 2; i++) {
                rs_run[i][0] = rs_run[i][0] * scO + rs[i][0] * scN;
                rs_run[i][1] = rs_run[i][1] * scO + rs[i][1] * scN;
            }
            m_run = M2;
        }

        // col partials: same wm across warp -> plain sum over row-lanes
#pragma unroll
        for (int j = 0; j < 4; j++)
#pragma unroll
            for (int p = 0; p < 2; p++) {
                float v = cs[j][p];
                v += __shfl_xor_sync(0xFFFFFFFFu, v, 4);
                v += __shfl_xor_sync(0xFFFFFFFFu, v, 8);
                v += __shfl_xor_sync(0xFFFFFFFFu, v, 16);
                if (lane < 4) {
                    int col_g = bx * 128 + nw * 32 + j * 8 + 2 * lane + p;
                    g_col_m[(size_t)col_g * 256 + by * 4 + mw] = wm;
                    g_col_s[(size_t)col_g * 256 + by * 4 + mw] = v;
                }
            }

        // masked raw-logit scatter (sparse)
#pragma unroll
        for (int i = 0; i < 2; i++)
#pragma unroll
            for (int h = 0; h < 2; h++) {
                unsigned w = mword[i][h];
                if (w) {
                    int row_g = by * 128 + mw * 32 + i * 16 + (lane >> 2) + 8 * h;
                    float sR = 0.f;
                    int any = 0;
#pragma unroll
                    for (int j = 0; j < 4; j++)
#pragma unroll
                        for (int p = 0; p < 2; p++) {
                            int bit = j * 8 + 2 * (lane & 3) + p;
                            if ((w >> bit) & 1u) {
                                float x = acc[i][j][2 * h + p];
                                sR += x;
                                any = 1;
                                atomicAdd(&g_colS[bx * 128 + nw * 32 + bit], x);
                            }
                        }
                    if (any) atomicAdd(&g_rowS[row_g], sR);
                }
            }

        __syncthreads();
        buf ^= 1;
    }

    // write row partials: reduce over the 4 lanes sharing a row
#pragma unroll
    for (int i = 0; i < 2; i++)
#pragma unroll
        for (int h = 0; h < 2; h++) {
            float v = rs_run[i][h];
            v += __shfl_xor_sync(0xFFFFFFFFu, v, 1);
            v += __shfl_xor_sync(0xFFFFFFFFu, v, 2);
            if ((lane & 3) == 0) {
                int row_g = by * 128 + mw * 32 + i * 16 + (lane >> 2) + 8 * h;
                g_row_m[(size_t)row_g * 32 + gx * 4 + nw] = m_run;
                g_row_s[(size_t)row_g * 32 + gx * 4 + nw] = v;
            }
        }
}

// ---------------- column mask popcounts ------------------------------------
__global__ void __launch_bounds__(256) col_cnt_kernel() {
    __shared__ float sc[8][32];
    int t = threadIdx.x, warp = t >> 5, lane = t & 31;
    int b = blockIdx.x;
    float c = 0.f;
    for (int r = warp; r < C_IDS; r += 8) {
        unsigned w = g_mask[(size_t)r * (W_IDS / 32) + b];
        c += (float)((w >> lane) & 1u);
    }
    sc[warp][lane] = c;
    __syncthreads();
    if (warp == 0) {
        float x = sc[0][lane];
#pragma unroll
        for (int i = 1; i < 8; i++) x += sc[i][lane];
        g_colCnt[b * 32 + lane] = x;
    }
}

// ---------------- row finalize: merge 32 (m,s) + popcount -------------------
__global__ void __launch_bounds__(256) row_final_kernel() {
    __shared__ float part[8];
    int t = threadIdx.x, warp = t >> 5, lane = t & 31;
    int row = blockIdx.x * 8 + warp;

    float m = g_row_m[(size_t)row * 32 + lane];
    float s = g_row_s[(size_t)row * 32 + lane];
#pragma unroll
    for (int o = 16; o >= 1; o >>= 1) {
        float mo = __shfl_xor_sync(0xFFFFFFFFu, m, o);
        float so = __shfl_xor_sync(0xFFFFFFFFu, s, o);
        float M = fmaxf(m, mo);
        s = s * __expf(m - M) + so * __expf(mo - M);
        m = M;
    }

    float cnt = 0.f;
    for (int k = lane; k < W_IDS / 32; k += 32)
        cnt += (float)__popc(g_mask[(size_t)row * (W_IDS / 32) + k]);
#pragma unroll
    for (int o = 16; o >= 1; o >>= 1)
        cnt += __shfl_xor_sync(0xFFFFFFFFu, cnt, o);

    if (lane == 0) {
        float lse = m + logf(s);
        part[warp] = (g_rowS[row] - cnt * lse) / fmaxf(cnt, 1.f);
    }
    __syncthreads();
    if (t == 0) {
        float x = 0.f;
#pragma unroll
        for (int i = 0; i < 8; i++) x += part[i];
        atomicAdd(&g_acc[1], x);
    }
}

// ---------------- col finalize: merge 256 (m,s) -----------------------------
__global__ void __launch_bounds__(256) col_final_kernel() {
    __shared__ float part[8];
    int t = threadIdx.x, warp = t >> 5, lane = t & 31;
    int col = blockIdx.x * 8 + warp;
    size_t base = (size_t)col * 256;

    float m = -3.0e38f, s = 0.f;
#pragma unroll
    for (int k = 0; k < 8; k++) {
        float m1 = g_col_m[base + k * 32 + lane];
        float s1 = g_col_s[base + k * 32 + lane];
        float M = fmaxf(m, m1);
        s = s * __expf(m - M) + s1 * __expf(m1 - M);
        m = M;
    }
#pragma unroll
    for (int o = 16; o >= 1; o >>= 1) {
        float mo = __shfl_xor_sync(0xFFFFFFFFu, m, o);
        float so = __shfl_xor_sync(0xFFFFFFFFu, s, o);
        float M = fmaxf(m, mo);
        s = s * __expf(m - M) + so * __expf(mo - M);
        m = M;
    }

    if (lane == 0) {
        float cnt = g_colCnt[col];
        float lse = m + logf(s);
        part[warp] = (g_colS[col] - cnt * lse) / fmaxf(cnt, 1.f);
    }
    __syncthreads();
    if (t == 0) {
        float x = 0.f;
#pragma unroll
        for (int i = 0; i < 8; i++) x += part[i];
        atomicAdd(&g_acc[0], x);
    }
}

__global__ void final_kernel(float* out) {
    out[0] = -(A0 * g_acc[0] / (float)W_IDS + A1 * g_acc[1] / (float)C_IDS);
}

// ---------------- launch -------------------------------------------------------
extern "C" void kernel_launch(void* const* d_in, const int* in_sizes, int n_in,
                              void* d_out, int out_size) {
    const float* f1   = (const float*)d_in[0];
    const float* f2   = (const float*)d_in[1];
    const int*   csv  = (const int*)d_in[2];
    const int*   wiki = (const int*)d_in[3];
    int n = in_sizes[2];

    static int attr_set = 0;
    if (!attr_set) {
        cudaFuncSetAttribute(gemm_kernel, cudaFuncAttributeMaxDynamicSharedMemorySize,
                             SMEM_BYTES);
        attr_set = 1;
    }

    zero_kernel<<<2048, 256>>>();
    scatter_kernel<<<(n + 7) / 8, 256>>>(f1, f2, csv, wiki, n);
    finalize_emb_kernel<<<(C_IDS * DIM + 255) / 256, 256>>>();

    gemm_kernel<<<dim3(8, 64), NTHREADS, SMEM_BYTES>>>();

    col_cnt_kernel<<<W_IDS / 32, 256>>>();
    row_final_kernel<<<C_IDS / 8, 256>>>();
    col_final_kernel<<<W_IDS / 8, 256>>>();
    final_kernel<<<1, 1>>>((float*)d_out);
}

// round 7
// speedup vs baseline: 3.6384x; 1.8735x over previous
#include <cuda_runtime.h>
#include <cuda_fp16.h>
#include <math.h>
#include <stdint.h>

#define C_IDS 8192
#define W_IDS 8192
#define DIM 128
#define TEMP_INV 10.0f   // 1 / temperature(0.1)
#define A0 0.5f
#define A1 0.5f

// ---------------- device scratch ----------------------------------------
__device__ float    g_csv_sum[C_IDS * DIM];
__device__ float    g_wiki_sum[W_IDS * DIM];
__device__ float    g_csv_cnt[C_IDS];
__device__ float    g_wiki_cnt[W_IDS];
__device__ unsigned g_mask[(size_t)C_IDS * (W_IDS / 32)];   // 8 MB bitmask
// fragment-major fp16 operands (filled by conv kernels)
__device__ unsigned g_Afrag[(size_t)C_IDS * DIM / 2];   // 2 MB
__device__ unsigned g_Bfrag[(size_t)W_IDS * DIM / 2];   // 2 MB
__device__ float    g_row_m[(size_t)C_IDS * 16];    // (gx,nw) partials
__device__ float    g_row_s[(size_t)C_IDS * 16];
__device__ float    g_col_m[(size_t)W_IDS * 256];   // (by,mw) partials
__device__ float    g_col_s[(size_t)W_IDS * 256];
__device__ float    g_rowS[C_IDS];    // masked logit sums
__device__ float    g_colS[W_IDS];
__device__ float    g_colCnt[W_IDS];
__device__ float    g_acc[2];

// ---------------- zero kernel --------------------------------------------
__global__ void zero_kernel() {
    size_t i = (size_t)blockIdx.x * blockDim.x + threadIdx.x;
    size_t stride = (size_t)gridDim.x * blockDim.x;
    for (size_t j = i; j < (size_t)C_IDS * DIM; j += stride) {
        g_csv_sum[j]  = 0.f;
        g_wiki_sum[j] = 0.f;
    }
    for (size_t j = i; j < C_IDS; j += stride) {
        g_csv_cnt[j]  = 0.f;
        g_wiki_cnt[j] = 0.f;
        g_rowS[j]     = 0.f;
        g_colS[j]     = 0.f;
    }
    for (size_t j = i; j < (size_t)C_IDS * (W_IDS / 32); j += stride)
        g_mask[j] = 0u;
    if (i < 2) g_acc[i] = 0.f;
}

// ---------------- segment scatter-add + mask build ------------------------
__global__ void __launch_bounds__(256) scatter_kernel(
    const float* __restrict__ f1, const float* __restrict__ f2,
    const int* __restrict__ csv, const int* __restrict__ wiki, int n)
{
    int warp = threadIdx.x >> 5, lane = threadIdx.x & 31;
    int row = blockIdx.x * 8 + warp;
    if (row >= n) return;
    int c = csv[row];
    int w = wiki[row];

    float4 a = reinterpret_cast<const float4*>(f1 + (size_t)row * DIM)[lane];
    float4 b = reinterpret_cast<const float4*>(f2 + (size_t)row * DIM)[lane];

    float* cs = g_csv_sum + (size_t)c * DIM + lane * 4;
    atomicAdd(cs + 0, a.x); atomicAdd(cs + 1, a.y);
    atomicAdd(cs + 2, a.z); atomicAdd(cs + 3, a.w);

    float* ws = g_wiki_sum + (size_t)w * DIM + lane * 4;
    atomicAdd(ws + 0, b.x); atomicAdd(ws + 1, b.y);
    atomicAdd(ws + 2, b.z); atomicAdd(ws + 3, b.w);

    if (lane == 0) {
        atomicAdd(&g_csv_cnt[c], 1.f);
        atomicAdd(&g_wiki_cnt[w], 1.f);
        atomicOr(&g_mask[(size_t)c * (W_IDS / 32) + (w >> 5)], 1u << (w & 31));
    }
}

// ---------------- means -> fp16 fragment-major conversion -----------------
// A frag u32 index: (((tile*8 + mt)*8 + ks)*32 + lane)*4 + reg
//   row = tile*128 + mt*16 + (lane>>2) + 8*(reg&1)
//   col = ks*16 + (lane&3)*2 + 8*(reg>>1)    (halves: col, col+1)
__global__ void convA_kernel() {
    int gid = blockIdx.x * blockDim.x + threadIdx.x;   // 0 .. 524287
    int reg  = gid & 3;
    int lane = (gid >> 2) & 31;
    int ks   = (gid >> 7) & 7;
    int mt   = (gid >> 10) & 7;
    int tile = gid >> 13;
    int r = tile * 128 + mt * 16 + (lane >> 2) + 8 * (reg & 1);
    int c = ks * 16 + (lane & 3) * 2 + 8 * (reg >> 1);
    float inv = TEMP_INV / fmaxf(g_csv_cnt[r], 1.f);
    float x0 = g_csv_sum[r * DIM + c]     * inv;
    float x1 = g_csv_sum[r * DIM + c + 1] * inv;
    __half2 h = __floats2half2_rn(x0, x1);
    g_Afrag[gid] = *reinterpret_cast<unsigned*>(&h);
}

// B frag u32 index: (((tile*16 + nt)*8 + ks)*32 + lane)*2 + reg
//   n = tile*128 + nt*8 + (lane>>2)
//   k = ks*16 + (lane&3)*2 + 8*reg          (halves: k, k+1)
__global__ void convB_kernel() {
    int gid = blockIdx.x * blockDim.x + threadIdx.x;   // 0 .. 524287
    int reg  = gid & 1;
    int lane = (gid >> 1) & 31;
    int ks   = (gid >> 6) & 7;
    int nt   = (gid >> 9) & 15;
    int tile = gid >> 13;
    int n = tile * 128 + nt * 8 + (lane >> 2);
    int k = ks * 16 + (lane & 3) * 2 + 8 * reg;
    float inv = 1.f / fmaxf(g_wiki_cnt[n], 1.f);
    float x0 = g_wiki_sum[n * DIM + k]     * inv;
    float x1 = g_wiki_sum[n * DIM + k + 1] * inv;
    __half2 h = __floats2half2_rn(x0, x1);
    g_Bfrag[gid] = *reinterpret_cast<unsigned*>(&h);
}

// ---------------- mma + cp.async helpers -----------------------------------
__device__ __forceinline__ void mma_f16(float* d, const uint4& a, const uint2& b) {
    asm volatile(
        "mma.sync.aligned.m16n8k16.row.col.f32.f16.f16.f32 "
        "{%0,%1,%2,%3}, {%4,%5,%6,%7}, {%8,%9}, {%0,%1,%2,%3};"
        : "+f"(d[0]), "+f"(d[1]), "+f"(d[2]), "+f"(d[3])
        : "r"(a.x), "r"(a.y), "r"(a.z), "r"(a.w), "r"(b.x), "r"(b.y));
}
__device__ __forceinline__ uint32_t smem_u32(const void* p) {
    uint32_t a;
    asm("{ .reg .u64 t; cvta.to.shared.u64 t, %1; cvt.u32.u64 %0, t; }" : "=r"(a) : "l"(p));
    return a;
}
__device__ __forceinline__ void cp16(uint32_t s, const void* g) {
    asm volatile("cp.async.cg.shared.global [%0], [%1], 16;" :: "r"(s), "l"(g));
}
#define CP_COMMIT() asm volatile("cp.async.commit_group;" ::: "memory")
#define CP_WAIT1()  asm volatile("cp.async.wait_group 1;" ::: "memory")
#define CP_WAIT0()  asm volatile("cp.async.wait_group 0;" ::: "memory")

// ---------------- smem layout ----------------------------------------------
#define SM_A   0
#define SM_B0  32768
#define SM_B1  65536
#define SMEM_BYTES 98304
#define NTHREADS 256

// ---------------- fp16 tensor GEMM + fused shifted-exp partials -------------
// grid (8, 64): CTA = row-tile by (128 rows) x col tiles gx*8..gx*8+7.
// 8 warps: mw = wid>>1 (4 in M, 32 rows), nw = wid&1 (2 in N, 64 cols).
// acc[i][j][r]: row = mw*32 + i*16 + (lane>>2) + 8*(r>>1)
//              col = nw*64 + j*8 + 2*(lane&3) + (r&1)
__global__ void __launch_bounds__(NTHREADS, 2) gemm_kernel() {
    extern __shared__ char smem[];
    uint32_t sb = smem_u32(smem);
    int t = threadIdx.x, wid = t >> 5, lane = t & 31;
    int mw = wid >> 1, nw = wid & 1;
    int gx = blockIdx.x, by = blockIdx.y;

    // preload A (32KB) + B0 + B1 via cp.async
    {
        const char* Ag = (const char*)(g_Afrag + (size_t)by * 8192);
        for (int i = t; i < 2048; i += NTHREADS)
            cp16(sb + SM_A + i * 16, Ag + i * 16);
        const char* Bg = (const char*)(g_Bfrag + (size_t)(gx * 8) * 8192);
        for (int i = t; i < 2048; i += NTHREADS)
            cp16(sb + SM_B0 + i * 16, Bg + i * 16);
        CP_COMMIT();                                   // G0: A + B0
        const char* Bg1 = (const char*)(g_Bfrag + (size_t)(gx * 8 + 1) * 8192);
        for (int i = t; i < 2048; i += NTHREADS)
            cp16(sb + SM_B1 + i * 16, Bg1 + i * 16);
        CP_COMMIT();                                   // G1: B1
    }

    float m_run = -3.0e38f;
    float rs_run[2][2];
    rs_run[0][0] = rs_run[0][1] = rs_run[1][0] = rs_run[1][1] = 0.f;

    for (int tt = 0; tt < 8; tt++) {
        int bx = gx * 8 + tt;
        if (tt < 7) CP_WAIT1(); else CP_WAIT0();
        __syncthreads();

        const uint4* Af = (const uint4*)(smem + SM_A);
        const uint2* Bf = (const uint2*)(smem + ((tt & 1) ? SM_B1 : SM_B0));

        float acc[2][8][4];
#pragma unroll
        for (int i = 0; i < 2; i++)
#pragma unroll
            for (int j = 0; j < 8; j++)
#pragma unroll
                for (int r = 0; r < 4; r++) acc[i][j][r] = 0.f;

#pragma unroll
        for (int ks = 0; ks < 8; ks++) {
            uint4 a[2];
            uint2 b[8];
#pragma unroll
            for (int i = 0; i < 2; i++)
                a[i] = Af[((mw * 2 + i) * 8 + ks) * 32 + lane];
#pragma unroll
            for (int j = 0; j < 8; j++)
                b[j] = Bf[((nw * 8 + j) * 8 + ks) * 32 + lane];
#pragma unroll
            for (int i = 0; i < 2; i++)
#pragma unroll
                for (int j = 0; j < 8; j++)
                    mma_f16(acc[i][j], a[i], b[j]);
        }
        __syncthreads();   // all warps done reading this B buffer

        // prefetch tile tt+2 into the buffer just consumed
        if (tt < 6) {
            const char* Bg = (const char*)(g_Bfrag + (size_t)(bx + 2) * 8192);
            uint32_t dst = sb + ((tt & 1) ? SM_B1 : SM_B0);
            for (int i = t; i < 2048; i += NTHREADS)
                cp16(dst + i * 16, Bg + i * 16);
        }
        CP_COMMIT();

        // prefetch mask words (2 per row group)
        unsigned mword[2][2][2];
#pragma unroll
        for (int i = 0; i < 2; i++)
#pragma unroll
            for (int h = 0; h < 2; h++) {
                int row_g = by * 128 + mw * 32 + i * 16 + (lane >> 2) + 8 * h;
                mword[i][h][0] = g_mask[(size_t)row_g * (W_IDS / 32) + bx * 4 + nw * 2];
                mword[i][h][1] = g_mask[(size_t)row_g * (W_IDS / 32) + bx * 4 + nw * 2 + 1];
            }

        // ---- warp-tile max (warp-uniform shift) ---------------------------
        float wm = acc[0][0][0];
#pragma unroll
        for (int i = 0; i < 2; i++)
#pragma unroll
            for (int j = 0; j < 8; j++)
#pragma unroll
                for (int r = 0; r < 4; r++) wm = fmaxf(wm, acc[i][j][r]);
#pragma unroll
        for (int o = 16; o >= 1; o >>= 1)
            wm = fmaxf(wm, __shfl_xor_sync(0xFFFFFFFFu, wm, o));

        // one exp per element; row & col sums from same e
        float rs[2][2], cs[8][2];
#pragma unroll
        for (int i = 0; i < 2; i++) { rs[i][0] = rs[i][1] = 0.f; }
#pragma unroll
        for (int j = 0; j < 8; j++) { cs[j][0] = cs[j][1] = 0.f; }
#pragma unroll
        for (int i = 0; i < 2; i++)
#pragma unroll
            for (int j = 0; j < 8; j++)
#pragma unroll
                for (int r = 0; r < 4; r++) {
                    float e = __expf(acc[i][j][r] - wm);
                    rs[i][r >> 1] += e;
                    cs[j][r & 1]  += e;
                }

        // online row merge across tiles
        {
            float M2 = fmaxf(m_run, wm);
            float scO = __expf(m_run - M2);
            float scN = __expf(wm - M2);
#pragma unroll
            for (int i = 0; i < 2; i++) {
                rs_run[i][0] = rs_run[i][0] * scO + rs[i][0] * scN;
                rs_run[i][1] = rs_run[i][1] * scO + rs[i][1] * scN;
            }
            m_run = M2;
        }

        // col partials
#pragma unroll
        for (int j = 0; j < 8; j++)
#pragma unroll
            for (int p = 0; p < 2; p++) {
                float v = cs[j][p];
                v += __shfl_xor_sync(0xFFFFFFFFu, v, 4);
                v += __shfl_xor_sync(0xFFFFFFFFu, v, 8);
                v += __shfl_xor_sync(0xFFFFFFFFu, v, 16);
                if (lane < 4) {
                    int col_g = bx * 128 + nw * 64 + j * 8 + 2 * lane + p;
                    g_col_m[(size_t)col_g * 256 + by * 4 + mw] = wm;
                    g_col_s[(size_t)col_g * 256 + by * 4 + mw] = v;
                }
            }

        // masked raw-logit scatter (sparse)
#pragma unroll
        for (int i = 0; i < 2; i++)
#pragma unroll
            for (int h = 0; h < 2; h++) {
                int row_g = by * 128 + mw * 32 + i * 16 + (lane >> 2) + 8 * h;
                float sR = 0.f;
                int any = 0;
#pragma unroll
                for (int ww = 0; ww < 2; ww++) {
                    unsigned w = mword[i][h][ww];
                    if (w) {
#pragma unroll
                        for (int jj = 0; jj < 4; jj++)
#pragma unroll
                            for (int p = 0; p < 2; p++) {
                                int bit = jj * 8 + 2 * (lane & 3) + p;
                                if ((w >> bit) & 1u) {
                                    int j = ww * 4 + jj;
                                    float x = acc[i][j][2 * h + p];
                                    sR += x;
                                    any = 1;
                                    atomicAdd(&g_colS[bx * 128 + nw * 64 + j * 8 +
                                                      2 * (lane & 3) + p], x);
                                }
                            }
                    }
                }
                if (any) atomicAdd(&g_rowS[row_g], sR);
            }
    }

    // write row partials: reduce over the 4 lanes sharing a row
#pragma unroll
    for (int i = 0; i < 2; i++)
#pragma unroll
        for (int h = 0; h < 2; h++) {
            float v = rs_run[i][h];
            v += __shfl_xor_sync(0xFFFFFFFFu, v, 1);
            v += __shfl_xor_sync(0xFFFFFFFFu, v, 2);
            if ((lane & 3) == 0) {
                int row_g = by * 128 + mw * 32 + i * 16 + (lane >> 2) + 8 * h;
                g_row_m[(size_t)row_g * 16 + gx * 2 + nw] = m_run;
                g_row_s[(size_t)row_g * 16 + gx * 2 + nw] = v;
            }
        }
}

// ---------------- column mask popcounts ------------------------------------
__global__ void __launch_bounds__(256) col_cnt_kernel() {
    __shared__ float sc[8][32];
    int t = threadIdx.x, warp = t >> 5, lane = t & 31;
    int b = blockIdx.x;
    float c = 0.f;
    for (int r = warp; r < C_IDS; r += 8) {
        unsigned w = g_mask[(size_t)r * (W_IDS / 32) + b];
        c += (float)((w >> lane) & 1u);
    }
    sc[warp][lane] = c;
    __syncthreads();
    if (warp == 0) {
        float x = sc[0][lane];
#pragma unroll
        for (int i = 1; i < 8; i++) x += sc[i][lane];
        g_colCnt[b * 32 + lane] = x;
    }
}

// ---------------- row finalize: merge 16 (m,s) + popcount -------------------
__global__ void __launch_bounds__(256) row_final_kernel() {
    __shared__ float part[8];
    int t = threadIdx.x, warp = t >> 5, lane = t & 31;
    int row = blockIdx.x * 8 + warp;

    float m = -3.0e38f, s = 0.f;
    if (lane < 16) {
        m = g_row_m[(size_t)row * 16 + lane];
        s = g_row_s[(size_t)row * 16 + lane];
    }
#pragma unroll
    for (int o = 8; o >= 1; o >>= 1) {
        float mo = __shfl_xor_sync(0xFFFFFFFFu, m, o, 16);
        float so = __shfl_xor_sync(0xFFFFFFFFu, s, o, 16);
        float M = fmaxf(m, mo);
        s = s * __expf(m - M) + so * __expf(mo - M);
        m = M;
    }

    float cnt = 0.f;
    for (int k = lane; k < W_IDS / 32; k += 32)
        cnt += (float)__popc(g_mask[(size_t)row * (W_IDS / 32) + k]);
#pragma unroll
    for (int o = 16; o >= 1; o >>= 1)
        cnt += __shfl_xor_sync(0xFFFFFFFFu, cnt, o);

    if (lane == 0) {
        float lse = m + logf(s);
        part[warp] = (g_rowS[row] - cnt * lse) / fmaxf(cnt, 1.f);
    }
    __syncthreads();
    if (t == 0) {
        float x = 0.f;
#pragma unroll
        for (int i = 0; i < 8; i++) x += part[i];
        atomicAdd(&g_acc[1], x);
    }
}

// ---------------- col finalize: merge 256 (m,s) -----------------------------
__global__ void __launch_bounds__(256) col_final_kernel() {
    __shared__ float part[8];
    int t = threadIdx.x, warp = t >> 5, lane = t & 31;
    int col = blockIdx.x * 8 + warp;
    size_t base = (size_t)col * 256;

    float m = -3.0e38f, s = 0.f;
#pragma unroll
    for (int k = 0; k < 8; k++) {
        float m1 = g_col_m[base + k * 32 + lane];
        float s1 = g_col_s[base + k * 32 + lane];
        float M = fmaxf(m, m1);
        s = s * __expf(m - M) + s1 * __expf(m1 - M);
        m = M;
    }
#pragma unroll
    for (int o = 16; o >= 1; o >>= 1) {
        float mo = __shfl_xor_sync(0xFFFFFFFFu, m, o);
        float so = __shfl_xor_sync(0xFFFFFFFFu, s, o);
        float M = fmaxf(m, mo);
        s = s * __expf(m - M) + so * __expf(mo - M);
        m = M;
    }

    if (lane == 0) {
        float cnt = g_colCnt[col];
        float lse = m + logf(s);
        part[warp] = (g_colS[col] - cnt * lse) / fmaxf(cnt, 1.f);
    }
    __syncthreads();
    if (t == 0) {
        float x = 0.f;
#pragma unroll
        for (int i = 0; i < 8; i++) x += part[i];
        atomicAdd(&g_acc[0], x);
    }
}

__global__ void final_kernel(float* out) {
    out[0] = -(A0 * g_acc[0] / (float)W_IDS + A1 * g_acc[1] / (float)C_IDS);
}

// ---------------- launch -------------------------------------------------------
extern "C" void kernel_launch(void* const* d_in, const int* in_sizes, int n_in,
                              void* d_out, int out_size) {
    const float* f1   = (const float*)d_in[0];
    const float* f2   = (const float*)d_in[1];
    const int*   csv  = (const int*)d_in[2];
    const int*   wiki = (const int*)d_in[3];
    int n = in_sizes[2];

    static int attr_set = 0;
    if (!attr_set) {
        cudaFuncSetAttribute(gemm_kernel, cudaFuncAttributeMaxDynamicSharedMemorySize,
                             SMEM_BYTES);
        attr_set = 1;
    }

    zero_kernel<<<2048, 256>>>();
    scatter_kernel<<<(n + 7) / 8, 256>>>(f1, f2, csv, wiki, n);
    convA_kernel<<<2048, 256>>>();
    convB_kernel<<<2048, 256>>>();

    gemm_kernel<<<dim3(8, 64), NTHREADS, SMEM_BYTES>>>();

    col_cnt_kernel<<<W_IDS / 32, 256>>>();
    row_final_kernel<<<C_IDS / 8, 256>>>();
    col_final_kernel<<<W_IDS / 8, 256>>>();
    final_kernel<<<1, 1>>>((float*)d_out);
}

// round 8
// speedup vs baseline: 4.6009x; 1.2645x over previous
#include <cuda_runtime.h>
#include <cuda_fp16.h>
#include <math.h>
#include <stdint.h>

#define C_IDS 8192
#define W_IDS 8192
#define DIM 128
#define TEMP_INV 10.0f   // 1 / temperature(0.1)
#define A0 0.5f
#define A1 0.5f

// ---------------- device scratch ----------------------------------------
__device__ float    g_csv_sum[C_IDS * DIM];
__device__ float    g_wiki_sum[W_IDS * DIM];
__device__ float    g_csv_cnt[C_IDS];
__device__ float    g_wiki_cnt[W_IDS];
__device__ unsigned g_mask[(size_t)C_IDS * (W_IDS / 32)];   // 8 MB bitmask
// fragment-major fp16 operands (filled by conv kernels)
__device__ unsigned g_Afrag[(size_t)C_IDS * DIM / 2];   // 2 MB
__device__ unsigned g_Bfrag[(size_t)W_IDS * DIM / 2];   // 2 MB
__device__ float    g_row_m[(size_t)C_IDS * 16];    // (gx,nw) partials
__device__ float    g_row_s[(size_t)C_IDS * 16];
__device__ float    g_col_m[(size_t)W_IDS * 256];   // (by,mw) partials
__device__ float    g_col_s[(size_t)W_IDS * 256];
__device__ float    g_rowS[C_IDS];    // masked logit sums
__device__ float    g_colS[W_IDS];
__device__ float    g_colCnt[W_IDS];
__device__ float    g_acc[2];

// ---------------- zero kernel (float4 stores, one wave) -------------------
__global__ void __launch_bounds__(256) zero_kernel() {
    size_t i = (size_t)blockIdx.x * blockDim.x + threadIdx.x;
    size_t stride = (size_t)gridDim.x * blockDim.x;
    float4 z4 = make_float4(0.f, 0.f, 0.f, 0.f);

    // embeddings: 2 * 1M floats = 512K float4
    float4* cs = reinterpret_cast<float4*>(g_csv_sum);
    float4* ws = reinterpret_cast<float4*>(g_wiki_sum);
    for (size_t j = i; j < (size_t)C_IDS * DIM / 4; j += stride) {
        cs[j] = z4;
        ws[j] = z4;
    }
    // mask: 2M words = 512K uint4
    uint4* mk = reinterpret_cast<uint4*>(g_mask);
    uint4 zu = make_uint4(0u, 0u, 0u, 0u);
    for (size_t j = i; j < (size_t)C_IDS * (W_IDS / 32) / 4; j += stride)
        mk[j] = zu;
    // small vectors
    for (size_t j = i; j < C_IDS; j += stride) {
        g_csv_cnt[j]  = 0.f;
        g_wiki_cnt[j] = 0.f;
        g_rowS[j]     = 0.f;
        g_colS[j]     = 0.f;
    }
    if (i < 2) g_acc[i] = 0.f;
}

// ---------------- segment scatter-add (vector RED) + mask build -----------
__device__ __forceinline__ void red_v4(float* addr, float4 v) {
    asm volatile("red.global.add.v4.f32 [%0], {%1, %2, %3, %4};"
                 :: "l"(addr), "f"(v.x), "f"(v.y), "f"(v.z), "f"(v.w)
                 : "memory");
}

__global__ void __launch_bounds__(256) scatter_kernel(
    const float* __restrict__ f1, const float* __restrict__ f2,
    const int* __restrict__ csv, const int* __restrict__ wiki, int n)
{
    int warp = threadIdx.x >> 5, lane = threadIdx.x & 31;
    int row = blockIdx.x * 8 + warp;
    if (row >= n) return;
    int c = csv[row];
    int w = wiki[row];

    float4 a = reinterpret_cast<const float4*>(f1 + (size_t)row * DIM)[lane];
    float4 b = reinterpret_cast<const float4*>(f2 + (size_t)row * DIM)[lane];

    red_v4(g_csv_sum + (size_t)c * DIM + lane * 4, a);
    red_v4(g_wiki_sum + (size_t)w * DIM + lane * 4, b);

    if (lane == 0) {
        atomicAdd(&g_csv_cnt[c], 1.f);
        atomicAdd(&g_wiki_cnt[w], 1.f);
        atomicOr(&g_mask[(size_t)c * (W_IDS / 32) + (w >> 5)], 1u << (w & 31));
    }
}

// ---------------- means -> fp16 fragment-major conversion -----------------
__global__ void convA_kernel() {
    int gid = blockIdx.x * blockDim.x + threadIdx.x;   // 0 .. 524287
    int reg  = gid & 3;
    int lane = (gid >> 2) & 31;
    int ks   = (gid >> 7) & 7;
    int mt   = (gid >> 10) & 7;
    int tile = gid >> 13;
    int r = tile * 128 + mt * 16 + (lane >> 2) + 8 * (reg & 1);
    int c = ks * 16 + (lane & 3) * 2 + 8 * (reg >> 1);
    float inv = TEMP_INV / fmaxf(g_csv_cnt[r], 1.f);
    float x0 = g_csv_sum[r * DIM + c]     * inv;
    float x1 = g_csv_sum[r * DIM + c + 1] * inv;
    __half2 h = __floats2half2_rn(x0, x1);
    g_Afrag[gid] = *reinterpret_cast<unsigned*>(&h);
}

__global__ void convB_kernel() {
    int gid = blockIdx.x * blockDim.x + threadIdx.x;   // 0 .. 524287
    int reg  = gid & 1;
    int lane = (gid >> 1) & 31;
    int ks   = (gid >> 6) & 7;
    int nt   = (gid >> 9) & 15;
    int tile = gid >> 13;
    int n = tile * 128 + nt * 8 + (lane >> 2);
    int k = ks * 16 + (lane & 3) * 2 + 8 * reg;
    float inv = 1.f / fmaxf(g_wiki_cnt[n], 1.f);
    float x0 = g_wiki_sum[n * DIM + k]     * inv;
    float x1 = g_wiki_sum[n * DIM + k + 1] * inv;
    __half2 h = __floats2half2_rn(x0, x1);
    g_Bfrag[gid] = *reinterpret_cast<unsigned*>(&h);
}

// ---------------- mma + cp.async helpers -----------------------------------
__device__ __forceinline__ void mma_f16(float* d, const uint4& a, const uint2& b) {
    asm volatile(
        "mma.sync.aligned.m16n8k16.row.col.f32.f16.f16.f32 "
        "{%0,%1,%2,%3}, {%4,%5,%6,%7}, {%8,%9}, {%0,%1,%2,%3};"
        : "+f"(d[0]), "+f"(d[1]), "+f"(d[2]), "+f"(d[3])
        : "r"(a.x), "r"(a.y), "r"(a.z), "r"(a.w), "r"(b.x), "r"(b.y));
}
__device__ __forceinline__ uint32_t smem_u32(const void* p) {
    uint32_t a;
    asm("{ .reg .u64 t; cvta.to.shared.u64 t, %1; cvt.u32.u64 %0, t; }" : "=r"(a) : "l"(p));
    return a;
}
__device__ __forceinline__ void cp16(uint32_t s, const void* g) {
    asm volatile("cp.async.cg.shared.global [%0], [%1], 16;" :: "r"(s), "l"(g));
}
#define CP_COMMIT() asm volatile("cp.async.commit_group;" ::: "memory")
#define CP_WAIT1()  asm volatile("cp.async.wait_group 1;" ::: "memory")
#define CP_WAIT0()  asm volatile("cp.async.wait_group 0;" ::: "memory")

// ---------------- smem layout ----------------------------------------------
#define SM_A   0
#define SM_B0  32768
#define SM_B1  65536
#define SMEM_BYTES 98304
#define NTHREADS 256

// ---------------- fp16 tensor GEMM + fused shifted-exp partials -------------
// grid (8, 64): CTA = row-tile by (128 rows) x col tiles gx*8..gx*8+7.
// 8 warps: mw = wid>>1 (4 in M, 32 rows), nw = wid&1 (2 in N, 64 cols).
// acc[i][j][r]: row = mw*32 + i*16 + (lane>>2) + 8*(r>>1)
//              col = nw*64 + j*8 + 2*(lane&3) + (r&1)
__global__ void __launch_bounds__(NTHREADS, 2) gemm_kernel() {
    extern __shared__ char smem[];
    uint32_t sb = smem_u32(smem);
    int t = threadIdx.x, wid = t >> 5, lane = t & 31;
    int mw = wid >> 1, nw = wid & 1;
    int gx = blockIdx.x, by = blockIdx.y;

    // preload A (32KB) + B0 + B1 via cp.async
    {
        const char* Ag = (const char*)(g_Afrag + (size_t)by * 8192);
        for (int i = t; i < 2048; i += NTHREADS)
            cp16(sb + SM_A + i * 16, Ag + i * 16);
        const char* Bg = (const char*)(g_Bfrag + (size_t)(gx * 8) * 8192);
        for (int i = t; i < 2048; i += NTHREADS)
            cp16(sb + SM_B0 + i * 16, Bg + i * 16);
        CP_COMMIT();                                   // G0: A + B0
        const char* Bg1 = (const char*)(g_Bfrag + (size_t)(gx * 8 + 1) * 8192);
        for (int i = t; i < 2048; i += NTHREADS)
            cp16(sb + SM_B1 + i * 16, Bg1 + i * 16);
        CP_COMMIT();                                   // G1: B1
    }

    float m_run = -3.0e38f;
    float rs_run[2][2];
    rs_run[0][0] = rs_run[0][1] = rs_run[1][0] = rs_run[1][1] = 0.f;

    for (int tt = 0; tt < 8; tt++) {
        int bx = gx * 8 + tt;
        if (tt < 7) CP_WAIT1(); else CP_WAIT0();
        __syncthreads();

        const uint4* Af = (const uint4*)(smem + SM_A);
        const uint2* Bf = (const uint2*)(smem + ((tt & 1) ? SM_B1 : SM_B0));

        float acc[2][8][4];
#pragma unroll
        for (int i = 0; i < 2; i++)
#pragma unroll
            for (int j = 0; j < 8; j++)
#pragma unroll
                for (int r = 0; r < 4; r++) acc[i][j][r] = 0.f;

#pragma unroll
        for (int ks = 0; ks < 8; ks++) {
            uint4 a[2];
            uint2 b[8];
#pragma unroll
            for (int i = 0; i < 2; i++)
                a[i] = Af[((mw * 2 + i) * 8 + ks) * 32 + lane];
#pragma unroll
            for (int j = 0; j < 8; j++)
                b[j] = Bf[((nw * 8 + j) * 8 + ks) * 32 + lane];
#pragma unroll
            for (int i = 0; i < 2; i++)
#pragma unroll
                for (int j = 0; j < 8; j++)
                    mma_f16(acc[i][j], a[i], b[j]);
        }
        __syncthreads();   // all warps done reading this B buffer

        // prefetch tile tt+2 into the buffer just consumed
        if (tt < 6) {
            const char* Bg = (const char*)(g_Bfrag + (size_t)(bx + 2) * 8192);
            uint32_t dst = sb + ((tt & 1) ? SM_B1 : SM_B0);
            for (int i = t; i < 2048; i += NTHREADS)
                cp16(dst + i * 16, Bg + i * 16);
        }
        CP_COMMIT();

        // prefetch mask words (2 per row group)
        unsigned mword[2][2][2];
#pragma unroll
        for (int i = 0; i < 2; i++)
#pragma unroll
            for (int h = 0; h < 2; h++) {
                int row_g = by * 128 + mw * 32 + i * 16 + (lane >> 2) + 8 * h;
                mword[i][h][0] = g_mask[(size_t)row_g * (W_IDS / 32) + bx * 4 + nw * 2];
                mword[i][h][1] = g_mask[(size_t)row_g * (W_IDS / 32) + bx * 4 + nw * 2 + 1];
            }

        // ---- warp-tile max (warp-uniform shift) ---------------------------
        float wm = acc[0][0][0];
#pragma unroll
        for (int i = 0; i < 2; i++)
#pragma unroll
            for (int j = 0; j < 8; j++)
#pragma unroll
                for (int r = 0; r < 4; r++) wm = fmaxf(wm, acc[i][j][r]);
#pragma unroll
        for (int o = 16; o >= 1; o >>= 1)
            wm = fmaxf(wm, __shfl_xor_sync(0xFFFFFFFFu, wm, o));

        // one exp per element; row & col sums from same e
        float rs[2][2], cs[8][2];
#pragma unroll
        for (int i = 0; i < 2; i++) { rs[i][0] = rs[i][1] = 0.f; }
#pragma unroll
        for (int j = 0; j < 8; j++) { cs[j][0] = cs[j][1] = 0.f; }
#pragma unroll
        for (int i = 0; i < 2; i++)
#pragma unroll
            for (int j = 0; j < 8; j++)
#pragma unroll
                for (int r = 0; r < 4; r++) {
                    float e = __expf(acc[i][j][r] - wm);
                    rs[i][r >> 1] += e;
                    cs[j][r & 1]  += e;
                }

        // online row merge across tiles
        {
            float M2 = fmaxf(m_run, wm);
            float scO = __expf(m_run - M2);
            float scN = __expf(wm - M2);
#pragma unroll
            for (int i = 0; i < 2; i++) {
                rs_run[i][0] = rs_run[i][0] * scO + rs[i][0] * scN;
                rs_run[i][1] = rs_run[i][1] * scO + rs[i][1] * scN;
            }
            m_run = M2;
        }

        // col partials
#pragma unroll
        for (int j = 0; j < 8; j++)
#pragma unroll
            for (int p = 0; p < 2; p++) {
                float v = cs[j][p];
                v += __shfl_xor_sync(0xFFFFFFFFu, v, 4);
                v += __shfl_xor_sync(0xFFFFFFFFu, v, 8);
                v += __shfl_xor_sync(0xFFFFFFFFu, v, 16);
                if (lane < 4) {
                    int col_g = bx * 128 + nw * 64 + j * 8 + 2 * lane + p;
                    g_col_m[(size_t)col_g * 256 + by * 4 + mw] = wm;
                    g_col_s[(size_t)col_g * 256 + by * 4 + mw] = v;
                }
            }

        // masked raw-logit scatter (sparse)
#pragma unroll
        for (int i = 0; i < 2; i++)
#pragma unroll
            for (int h = 0; h < 2; h++) {
                int row_g = by * 128 + mw * 32 + i * 16 + (lane >> 2) + 8 * h;
                float sR = 0.f;
                int any = 0;
#pragma unroll
                for (int ww = 0; ww < 2; ww++) {
                    unsigned w = mword[i][h][ww];
                    if (w) {
#pragma unroll
                        for (int jj = 0; jj < 4; jj++)
#pragma unroll
                            for (int p = 0; p < 2; p++) {
                                int bit = jj * 8 + 2 * (lane & 3) + p;
                                if ((w >> bit) & 1u) {
                                    int j = ww * 4 + jj;
                                    float x = acc[i][j][2 * h + p];
                                    sR += x;
                                    any = 1;
                                    atomicAdd(&g_colS[bx * 128 + nw * 64 + j * 8 +
                                                      2 * (lane & 3) + p], x);
                                }
                            }
                    }
                }
                if (any) atomicAdd(&g_rowS[row_g], sR);
            }
    }

    // write row partials: reduce over the 4 lanes sharing a row
#pragma unroll
    for (int i = 0; i < 2; i++)
#pragma unroll
        for (int h = 0; h < 2; h++) {
            float v = rs_run[i][h];
            v += __shfl_xor_sync(0xFFFFFFFFu, v, 1);
            v += __shfl_xor_sync(0xFFFFFFFFu, v, 2);
            if ((lane & 3) == 0) {
                int row_g = by * 128 + mw * 32 + i * 16 + (lane >> 2) + 8 * h;
                g_row_m[(size_t)row_g * 16 + gx * 2 + nw] = m_run;
                g_row_s[(size_t)row_g * 16 + gx * 2 + nw] = v;
            }
        }
}

// ---------------- column mask popcounts ------------------------------------
__global__ void __launch_bounds__(256) col_cnt_kernel() {
    __shared__ float sc[8][32];
    int t = threadIdx.x, warp = t >> 5, lane = t & 31;
    int b = blockIdx.x;
    float c = 0.f;
    for (int r = warp; r < C_IDS; r += 8) {
        unsigned w = g_mask[(size_t)r * (W_IDS / 32) + b];
        c += (float)((w >> lane) & 1u);
    }
    sc[warp][lane] = c;
    __syncthreads();
    if (warp == 0) {
        float x = sc[0][lane];
#pragma unroll
        for (int i = 1; i < 8; i++) x += sc[i][lane];
        g_colCnt[b * 32 + lane] = x;
    }
}

// ---------------- row finalize: merge 16 (m,s) + popcount -------------------
__global__ void __launch_bounds__(256) row_final_kernel() {
    __shared__ float part[8];
    int t = threadIdx.x, warp = t >> 5, lane = t & 31;
    int row = blockIdx.x * 8 + warp;

    float m = -3.0e38f, s = 0.f;
    if (lane < 16) {
        m = g_row_m[(size_t)row * 16 + lane];
        s = g_row_s[(size_t)row * 16 + lane];
    }
#pragma unroll
    for (int o = 8; o >= 1; o >>= 1) {
        float mo = __shfl_xor_sync(0xFFFFFFFFu, m, o, 16);
        float so = __shfl_xor_sync(0xFFFFFFFFu, s, o, 16);
        float M = fmaxf(m, mo);
        s = s * __expf(m - M) + so * __expf(mo - M);
        m = M;
    }

    float cnt = 0.f;
    for (int k = lane; k < W_IDS / 32; k += 32)
        cnt += (float)__popc(g_mask[(size_t)row * (W_IDS / 32) + k]);
#pragma unroll
    for (int o = 16; o >= 1; o >>= 1)
        cnt += __shfl_xor_sync(0xFFFFFFFFu, cnt, o);

    if (lane == 0) {
        float lse = m + logf(s);
        part[warp] = (g_rowS[row] - cnt * lse) / fmaxf(cnt, 1.f);
    }
    __syncthreads();
    if (t == 0) {
        float x = 0.f;
#pragma unroll
        for (int i = 0; i < 8; i++) x += part[i];
        atomicAdd(&g_acc[1], x);
    }
}

// ---------------- col finalize: merge 256 (m,s) -----------------------------
__global__ void __launch_bounds__(256) col_final_kernel() {
    __shared__ float part[8];
    int t = threadIdx.x, warp = t >> 5, lane = t & 31;
    int col = blockIdx.x * 8 + warp;
    size_t base = (size_t)col * 256;

    float m = -3.0e38f, s = 0.f;
#pragma unroll
    for (int k = 0; k < 8; k++) {
        float m1 = g_col_m[base + k * 32 + lane];
        float s1 = g_col_s[base + k * 32 + lane];
        float M = fmaxf(m, m1);
        s = s * __expf(m - M) + s1 * __expf(m1 - M);
        m = M;
    }
#pragma unroll
    for (int o = 16; o >= 1; o >>= 1) {
        float mo = __shfl_xor_sync(0xFFFFFFFFu, m, o);
        float so = __shfl_xor_sync(0xFFFFFFFFu, s, o);
        float M = fmaxf(m, mo);
        s = s * __expf(m - M) + so * __expf(mo - M);
        m = M;
    }

    if (lane == 0) {
        float cnt = g_colCnt[col];
        float lse = m + logf(s);
        part[warp] = (g_colS[col] - cnt * lse) / fmaxf(cnt, 1.f);
    }
    __syncthreads();
    if (t == 0) {
        float x = 0.f;
#pragma unroll
        for (int i = 0; i < 8; i++) x += part[i];
        atomicAdd(&g_acc[0], x);
    }
}

__global__ void final_kernel(float* out) {
    out[0] = -(A0 * g_acc[0] / (float)W_IDS + A1 * g_acc[1] / (float)C_IDS);
}

// ---------------- launch -------------------------------------------------------
extern "C" void kernel_launch(void* const* d_in, const int* in_sizes, int n_in,
                              void* d_out, int out_size) {
    const float* f1   = (const float*)d_in[0];
    const float* f2   = (const float*)d_in[1];
    const int*   csv  = (const int*)d_in[2];
    const int*   wiki = (const int*)d_in[3];
    int n = in_sizes[2];

    static int attr_set = 0;
    if (!attr_set) {
        cudaFuncSetAttribute(gemm_kernel, cudaFuncAttributeMaxDynamicSharedMemorySize,
                             SMEM_BYTES);
        attr_set = 1;
    }

    zero_kernel<<<1184, 256>>>();
    scatter_kernel<<<(n + 7) / 8, 256>>>(f1, f2, csv, wiki, n);
    convA_kernel<<<2048, 256>>>();
    convB_kernel<<<2048, 256>>>();

    gemm_kernel<<<dim3(8, 64), NTHREADS, SMEM_BYTES>>>();

    col_cnt_kernel<<<W_IDS / 32, 256>>>();
    row_final_kernel<<<C_IDS / 8, 256>>>();
    col_final_kernel<<<W_IDS / 8, 256>>>();
    final_kernel<<<1, 1>>>((float*)d_out);
}